// round 5
// baseline (speedup 1.0000x reference)
#include <cuda_runtime.h>
#include <cuda_bf16.h>
#include <math.h>
#include <stdint.h>

// Problem constants
#define Bq 2
#define Tq 2048
#define Cq 1024
#define Hq 16
#define HDq 64
#define Mq (Bq*Tq)          // 4096

typedef unsigned long long u64;

// ---------------------------------------------------------------------------
// Device-global scratch (no allocation allowed)
// ---------------------------------------------------------------------------
__device__ float g_Q[(size_t)Bq*Hq*Tq*HDq];   // [B,H,T,HD]
__device__ float g_K[(size_t)Bq*Hq*Tq*HDq];
__device__ float g_V[(size_t)Bq*Hq*Tq*HDq];
__device__ float g_O[(size_t)Bq*Tq*Cq];       // merged heads [B,T,C]

// ---------------------------------------------------------------------------
// f32x2 helpers (sm_100+ base ISA packed fp32)
// ---------------------------------------------------------------------------
__device__ __forceinline__ uint32_t smem_u32(const void* p){
    uint32_t a;
    asm("{ .reg .u64 t; cvta.to.shared.u64 t, %1; cvt.u32.u64 %0, t; }"
        : "=r"(a) : "l"(p));
    return a;
}
__device__ __forceinline__ void ffma2(u64& d, u64 a, u64 b){
    asm("fma.rn.f32x2 %0, %1, %2, %0;" : "+l"(d) : "l"(a), "l"(b));
}
__device__ __forceinline__ void fmul2(u64& d, u64 a){
    asm("mul.rn.f32x2 %0, %0, %1;" : "+l"(d) : "l"(a));
}
__device__ __forceinline__ u64 pack2(float x, float y){
    u64 v; asm("mov.b64 %0, {%1, %2};" : "=l"(v) : "f"(x), "f"(y)); return v;
}
__device__ __forceinline__ void unpack2(u64 v, float& x, float& y){
    asm("mov.b64 {%0, %1}, %2;" : "=f"(x), "=f"(y) : "l"(v));
}
__device__ __forceinline__ u64 lds64(uint32_t a){
    u64 v; asm volatile("ld.shared.b64 %0, [%1];" : "=l"(v) : "r"(a)); return v;
}
__device__ __forceinline__ void lds128_2x64(u64& v0, u64& v1, uint32_t a){
    asm volatile("ld.shared.v2.u64 {%0, %1}, [%2];" : "=l"(v0), "=l"(v1) : "r"(a));
}

// ---------------------------------------------------------------------------
// FFMA2 SGEMM: out[4096,1024] = A * W + bias  (exact fp32)
// BM=BN=64, BK=16, 256 threads. Accumulators paired over M; B duplicated in
// smem so the (b,b) operand is one LDS.64. 8 FFMA2 + 5 LDS per k per thread.
// Thread (tx,ty): rows ty*4..+3 (2 pairs), cols {tx + 16*jp}, jp=0..3.
// ---------------------------------------------------------------------------
#define AS_STRIDE 68            // floats; 272B: 16B aligned rows for v2.u64
#define BS_STRIDE 130           // floats; 520B: 8B aligned rows

template<bool HEADOUT>
__global__ __launch_bounds__(256)
void proj_gemm(const float* __restrict__ A, const float* __restrict__ W,
               const float* __restrict__ bias, float* __restrict__ out)
{
    __shared__ float As[16*AS_STRIDE];   // As[k][m]
    __shared__ float Bs2[16*BS_STRIDE];  // Bs2[k][2n] = Bs2[k][2n+1] = W[k][n]

    const int tid = threadIdx.x;
    const int tx  = tid & 15;
    const int ty  = tid >> 4;
    const int bm  = blockIdx.y * 64;
    const int bn  = blockIdx.x * 64;

    const uint32_t asb = smem_u32(As);
    const uint32_t bsb = smem_u32(Bs2);

    u64 acc[2][4];
    #pragma unroll
    for (int p = 0; p < 2; p++)
        #pragma unroll
        for (int jp = 0; jp < 4; jp++) acc[p][jp] = 0ULL;

    const uint32_t aaddr = asb + (uint32_t)(ty * 4) * 4;
    uint32_t baddr[4];
    #pragma unroll
    for (int jp = 0; jp < 4; jp++)
        baddr[jp] = bsb + (uint32_t)(2 * (tx + 16 * jp)) * 4;

    for (int k0 = 0; k0 < Cq; k0 += 16) {
        // A tile 64x16 -> As[k][m] (transposed store)
        {
            int r  = tid >> 2;          // 0..63
            int c4 = tid & 3;           // 0..3
            float4 va = *reinterpret_cast<const float4*>(
                A + (size_t)(bm + r) * Cq + k0 + c4 * 4);
            As[(c4*4+0)*AS_STRIDE + r] = va.x;
            As[(c4*4+1)*AS_STRIDE + r] = va.y;
            As[(c4*4+2)*AS_STRIDE + r] = va.z;
            As[(c4*4+3)*AS_STRIDE + r] = va.w;
        }
        // B tile 16x64 -> duplicated pairs
        {
            int r  = tid >> 4;          // 0..15
            int c4 = tid & 15;          // 0..15
            float4 vb = *reinterpret_cast<const float4*>(
                W + (size_t)(k0 + r) * Cq + bn + c4 * 4);
            float2* dst = reinterpret_cast<float2*>(&Bs2[r*BS_STRIDE + c4*8]);
            dst[0] = make_float2(vb.x, vb.x);
            dst[1] = make_float2(vb.y, vb.y);
            dst[2] = make_float2(vb.z, vb.z);
            dst[3] = make_float2(vb.w, vb.w);
        }
        __syncthreads();

        #pragma unroll
        for (int k = 0; k < 16; k++) {
            u64 a0, a1;
            lds128_2x64(a0, a1, aaddr + (uint32_t)(k * AS_STRIDE) * 4);
            u64 bd[4];
            #pragma unroll
            for (int jp = 0; jp < 4; jp++)
                bd[jp] = lds64(baddr[jp] + (uint32_t)(k * BS_STRIDE) * 4);
            #pragma unroll
            for (int jp = 0; jp < 4; jp++) {
                ffma2(acc[0][jp], a0, bd[jp]);
                ffma2(acc[1][jp], a1, bd[jp]);
            }
        }
        __syncthreads();
    }

    // Epilogue: bias + store (coalesced across tx)
    #pragma unroll
    for (int jp = 0; jp < 4; jp++) {
        int n = bn + tx + 16 * jp;
        float bv = __ldg(&bias[n]);
        #pragma unroll
        for (int p = 0; p < 2; p++) {
            float v0, v1;
            unpack2(acc[p][jp], v0, v1);
            #pragma unroll
            for (int e = 0; e < 2; e++) {
                int m = bm + ty*4 + p*2 + e;
                float v = (e == 0 ? v0 : v1) + bv;
                if (HEADOUT) {
                    int b = m >> 11, tt = m & (Tq - 1);
                    int h = n >> 6,  dd = n & 63;
                    out[(((size_t)(b*Hq + h) * Tq) + tt) * HDq + dd] = v;
                } else {
                    out[(size_t)m * Cq + n] = v;
                }
            }
        }
    }
}

// ---------------------------------------------------------------------------
// Flash attention with FFMA2. 128 threads = 128 q rows per block; K/V tiles
// of 64 rows in smem; q,o packed f32x2 in registers; broadcast v2.u64 reads.
// ---------------------------------------------------------------------------
#define ATT_SMEM (64*64*4 + 64*64*4 + 128*65*4)   // Ks + Vs + Ss = 66048B

__global__ __launch_bounds__(128)
void attn_kernel(const float* __restrict__ Q, const float* __restrict__ K,
                 const float* __restrict__ V, float* __restrict__ O)
{
    extern __shared__ char sm[];
    float* Ks = reinterpret_cast<float*>(sm);
    float* Vs = Ks + 64*64;
    float* Ss = Vs + 64*64;
    const uint32_t ksb = smem_u32(Ks);
    const uint32_t vsb = smem_u32(Vs);

    const int tid = threadIdx.x;       // 0..127
    const int qt  = blockIdx.x * 128;
    const int h   = blockIdx.y;
    const int b   = blockIdx.z;

    const size_t headbase = ((size_t)(b*Hq + h) * Tq) * HDq;
    const float* Qb = Q + headbase;
    const float* Kb = K + headbase;
    const float* Vb = V + headbase;

    const float scale = 0.125f;        // 1/sqrt(64); folded into q
    u64 q2[32], o2[32];
    {
        const float4* q4 = reinterpret_cast<const float4*>(Qb + (size_t)(qt + tid) * HDq);
        #pragma unroll
        for (int c = 0; c < 16; c++) {
            float4 v = q4[c];
            q2[c*2+0] = pack2(v.x * scale, v.y * scale);
            q2[c*2+1] = pack2(v.z * scale, v.w * scale);
        }
        #pragma unroll
        for (int c = 0; c < 32; c++) o2[c] = 0ULL;
    }

    float m = -INFINITY, l = 0.f;

    for (int kt = 0; kt < Tq; kt += 64) {
        // K/V tile load: each tile = 4096 contiguous floats, 128 thr x 8 float4
        {
            const float4* Kg4 = reinterpret_cast<const float4*>(Kb + (size_t)kt * HDq);
            const float4* Vg4 = reinterpret_cast<const float4*>(Vb + (size_t)kt * HDq);
            float4* Ks4 = reinterpret_cast<float4*>(Ks);
            float4* Vs4 = reinterpret_cast<float4*>(Vs);
            #pragma unroll
            for (int s = 0; s < 8; s++) {
                Ks4[tid + s*128] = Kg4[tid + s*128];
                Vs4[tid + s*128] = Vg4[tid + s*128];
            }
        }
        __syncthreads();

        // S = (q*scale) . K^T, track tile max
        float tmax = -INFINITY;
        #pragma unroll 4
        for (int j = 0; j < 64; j++) {
            u64 s2 = 0ULL;
            uint32_t ka = ksb + (uint32_t)(j * 64) * 4;
            #pragma unroll
            for (int c = 0; c < 16; c++) {
                u64 k0, k1;
                lds128_2x64(k0, k1, ka + (uint32_t)c * 16);
                ffma2(s2, q2[c*2+0], k0);
                ffma2(s2, q2[c*2+1], k1);
            }
            float sx, sy;
            unpack2(s2, sx, sy);
            float s = sx + sy;
            Ss[tid*65 + j] = s;
            tmax = fmaxf(tmax, s);
        }

        float mnew  = fmaxf(m, tmax);
        float alpha = __expf(m - mnew);   // 0 on first tile
        l *= alpha;
        {
            u64 ad = pack2(alpha, alpha);
            #pragma unroll
            for (int c = 0; c < 32; c++) fmul2(o2[c], ad);
        }
        m = mnew;

        // P = exp(S - m); O += P * V
        #pragma unroll 2
        for (int j = 0; j < 64; j++) {
            float p = __expf(Ss[tid*65 + j] - mnew);
            l += p;
            u64 pd = pack2(p, p);
            uint32_t va = vsb + (uint32_t)(j * 64) * 4;
            #pragma unroll
            for (int c = 0; c < 16; c++) {
                u64 v0, v1;
                lds128_2x64(v0, v1, va + (uint32_t)c * 16);
                ffma2(o2[c*2+0], pd, v0);
                ffma2(o2[c*2+1], pd, v1);
            }
        }
        __syncthreads();
    }

    const float inv = 1.f / l;
    float4* Ob = reinterpret_cast<float4*>(
        O + ((size_t)(b*Tq) + qt + tid) * Cq + h * HDq);
    #pragma unroll
    for (int c = 0; c < 16; c++) {
        float x0, x1, x2, x3;
        unpack2(o2[c*2+0], x0, x1);
        unpack2(o2[c*2+1], x2, x3);
        float4 v; v.x = x0*inv; v.y = x1*inv; v.z = x2*inv; v.w = x3*inv;
        Ob[c] = v;
    }
}

// ---------------------------------------------------------------------------
// Launch
// ---------------------------------------------------------------------------
extern "C" void kernel_launch(void* const* d_in, const int* in_sizes, int n_in,
                              void* d_out, int out_size)
{
    (void)in_sizes; (void)n_in; (void)out_size;
    const float* queries = (const float*)d_in[0];
    const float* keys    = (const float*)d_in[1];
    const float* values  = (const float*)d_in[2];
    const float* Wq = (const float*)d_in[3];
    const float* bq = (const float*)d_in[4];
    const float* Wk = (const float*)d_in[5];
    const float* bk = (const float*)d_in[6];
    const float* Wv = (const float*)d_in[7];
    const float* bv = (const float*)d_in[8];
    const float* Wo = (const float*)d_in[9];
    const float* bo = (const float*)d_in[10];
    float* out = (float*)d_out;

    float *pQ, *pK, *pV, *pO;
    cudaGetSymbolAddress((void**)&pQ, g_Q);
    cudaGetSymbolAddress((void**)&pK, g_K);
    cudaGetSymbolAddress((void**)&pV, g_V);
    cudaGetSymbolAddress((void**)&pO, g_O);

    cudaFuncSetAttribute(attn_kernel, cudaFuncAttributeMaxDynamicSharedMemorySize, ATT_SMEM);

    dim3 gg(Cq/64, Mq/64);             // (16, 64)
    proj_gemm<true><<<gg, 256>>>(queries, Wq, bq, pQ);
    proj_gemm<true><<<gg, 256>>>(keys,    Wk, bk, pK);
    proj_gemm<true><<<gg, 256>>>(values,  Wv, bv, pV);

    dim3 ga(Tq/128, Hq, Bq);           // (16, 16, 2)
    attn_kernel<<<ga, 128, ATT_SMEM>>>(pQ, pK, pV, pO);

    proj_gemm<false><<<gg, 256>>>(pO, Wo, bo, out);
}

// round 6
// speedup vs baseline: 1.8607x; 1.8607x over previous
#include <cuda_runtime.h>
#include <cuda_bf16.h>
#include <math.h>
#include <stdint.h>

// Problem constants
#define Bq 2
#define Tq 2048
#define Cq 1024
#define Hq 16
#define HDq 64
#define Mq (Bq*Tq)          // 4096

// ---------------------------------------------------------------------------
// Device-global scratch (no allocation allowed)
// ---------------------------------------------------------------------------
__device__ float g_Qd[(size_t)Bq*Hq*HDq*Tq];  // [B,H,HD,T]  (d-major!)
__device__ float g_Kd[(size_t)Bq*Hq*HDq*Tq];  // [B,H,HD,T]  (d-major!)
__device__ float g_V [(size_t)Bq*Hq*Tq*HDq];  // [B,H,T,HD]
__device__ float g_O [(size_t)Bq*Tq*Cq];      // merged heads [B,T,C]

// ---------------------------------------------------------------------------
// Tiled SGEMM:  out = A[4096,1024] * W[1024,1024] + bias
// BM=BN=64, BK=16, 256 threads, 4x4 register blocking, vectorized LDS.
// MODE 0: flat [M,C] ; MODE 1: [B,H,T,HD] ; MODE 2: [B,H,HD,T] (d-major)
// ---------------------------------------------------------------------------
#define AST 68   // floats per As row (16B-aligned fragments)
#define BST 68

template<int MODE>
__global__ __launch_bounds__(256)
void proj_gemm(const float* __restrict__ A, const float* __restrict__ W,
               const float* __restrict__ bias, float* __restrict__ out)
{
    __shared__ float As[16*AST];   // As[k][m]
    __shared__ float Bs[16*BST];   // Bs[k][n]

    const int tid = threadIdx.x;
    const int tx  = tid & 15;          // N direction
    const int ty  = tid >> 4;          // M direction
    const int bm  = blockIdx.y * 64;
    const int bn  = blockIdx.x * 64;

    float acc[4][4] = {};

    for (int k0 = 0; k0 < Cq; k0 += 16) {
        // A tile 64x16 -> As[k][m] (transposed store)
        {
            int r  = tid >> 2;         // 0..63
            int c4 = tid & 3;          // 0..3
            float4 va = *reinterpret_cast<const float4*>(
                A + (size_t)(bm + r) * Cq + k0 + c4 * 4);
            As[(c4*4+0)*AST + r] = va.x;
            As[(c4*4+1)*AST + r] = va.y;
            As[(c4*4+2)*AST + r] = va.z;
            As[(c4*4+3)*AST + r] = va.w;
        }
        // B tile 16x64 -> Bs[k][n]
        {
            int r  = tid >> 4;         // 0..15
            int c4 = tid & 15;         // 0..15
            float4 vb = *reinterpret_cast<const float4*>(
                W + (size_t)(k0 + r) * Cq + bn + c4 * 4);
            *reinterpret_cast<float4*>(&Bs[r*BST + c4*4]) = vb;
        }
        __syncthreads();

        #pragma unroll
        for (int k = 0; k < 16; k++) {
            float4 a4 = *reinterpret_cast<const float4*>(&As[k*AST + ty*4]);
            float4 b4 = *reinterpret_cast<const float4*>(&Bs[k*BST + tx*4]);
            const float a[4] = {a4.x, a4.y, a4.z, a4.w};
            const float b[4] = {b4.x, b4.y, b4.z, b4.w};
            #pragma unroll
            for (int i = 0; i < 4; i++)
                #pragma unroll
                for (int j = 0; j < 4; j++)
                    acc[i][j] += a[i] * b[j];
        }
        __syncthreads();
    }

    // Epilogue: bias + store
    #pragma unroll
    for (int i = 0; i < 4; i++) {
        int m = bm + ty*4 + i;
        int b = m >> 11;               // m / T
        int t = m & (Tq - 1);
        #pragma unroll
        for (int j = 0; j < 4; j++) {
            int n = bn + tx*4 + j;
            float v = acc[i][j] + bias[n];
            if (MODE == 0) {
                out[(size_t)m * Cq + n] = v;
            } else {
                int h = n >> 6, d = n & 63;
                if (MODE == 1)
                    out[(((size_t)(b*Hq + h) * Tq) + t) * HDq + d] = v;
                else  // MODE 2: d-major
                    out[(((size_t)(b*Hq + h) * HDq) + d) * Tq + t] = v;
            }
        }
    }
}

// ---------------------------------------------------------------------------
// Flash attention as two register-tiled GEMMs.
// Block: 64 q rows of one (b,h), 256 threads, each owns a 4x4 tile.
// Qs/Kt in [d][t] layout (fed by d-major projections), Vs in [t][d].
// P aliases the K tile. Row stats via shfl.bfly over 16 tx lanes.
// ---------------------------------------------------------------------------
#define SST 68
#define ATT_SMEM (3*64*SST*4)     // Qs + Kt(/Ps) + Vs = 52224 B

__global__ __launch_bounds__(256)
void attn_kernel(const float* __restrict__ Qd, const float* __restrict__ Kd,
                 const float* __restrict__ V, float* __restrict__ O)
{
    extern __shared__ char smraw[];
    float* Qs = reinterpret_cast<float*>(smraw);       // [d][q]  64 x SST
    float* Kt = Qs + 64*SST;                           // [d][j] ; later Ps[j][q]
    float* Vs = Kt + 64*SST;                           // [j][d]

    const int tid = threadIdx.x;
    const int tx  = tid & 15;          // 4 cols each
    const int ty  = tid >> 4;          // 4 rows each
    const int qt  = blockIdx.x * 64;
    const int h   = blockIdx.y;
    const int b   = blockIdx.z;

    const size_t dmaj = ((size_t)(b*Hq + h) * HDq) * Tq;   // Qd/Kd base
    const float* Qb = Qd + dmaj;
    const float* Kb = Kd + dmaj;
    const float* Vb = V + ((size_t)(b*Hq + h) * Tq) * HDq;

    // Load Q tile [64d x 64t] (scaled) once
    {
        const float scale = 0.125f;    // 1/sqrt(64)
        #pragma unroll
        for (int s = 0; s < 4; s++) {
            int idx = tid + s*256;     // 0..1023
            int d = idx >> 4, j4 = idx & 15;
            float4 v = *reinterpret_cast<const float4*>(Qb + (size_t)d * Tq + qt + j4*4);
            v.x *= scale; v.y *= scale; v.z *= scale; v.w *= scale;
            *reinterpret_cast<float4*>(&Qs[d*SST + j4*4]) = v;
        }
    }

    float o[4][4] = {};
    float m[4]  = {-INFINITY, -INFINITY, -INFINITY, -INFINITY};
    float l[4]  = {0.f, 0.f, 0.f, 0.f};

    for (int kt0 = 0; kt0 < Tq; kt0 += 64) {
        __syncthreads();   // prev tile's smem reads (incl. Ps in Kt) done

        // Load K tile [64d x 64t] and V tile [64t x 64d]
        #pragma unroll
        for (int s = 0; s < 4; s++) {
            int idx = tid + s*256;
            int r = idx >> 4, c4 = idx & 15;
            float4 kv = *reinterpret_cast<const float4*>(Kb + (size_t)r * Tq + kt0 + c4*4);
            *reinterpret_cast<float4*>(&Kt[r*SST + c4*4]) = kv;
            float4 vv = *reinterpret_cast<const float4*>(Vb + (size_t)(kt0 + r) * HDq + c4*4);
            *reinterpret_cast<float4*>(&Vs[r*SST + c4*4]) = vv;
        }
        __syncthreads();

        // S = Q^T K : s[ii][jj], rows q=ty*4+ii, cols j=tx*4+jj
        float s[4][4] = {};
        #pragma unroll 8
        for (int c = 0; c < 64; c++) {
            float4 a4 = *reinterpret_cast<const float4*>(&Qs[c*SST + ty*4]);
            float4 b4 = *reinterpret_cast<const float4*>(&Kt[c*SST + tx*4]);
            const float a[4] = {a4.x, a4.y, a4.z, a4.w};
            const float bb[4] = {b4.x, b4.y, b4.z, b4.w};
            #pragma unroll
            for (int i = 0; i < 4; i++)
                #pragma unroll
                for (int j = 0; j < 4; j++)
                    s[i][j] += a[i] * bb[j];
        }
        __syncthreads();   // S-GEMM Kt reads complete before P overwrites

        // Online softmax (row stats across 16 tx lanes via bfly)
        float alpha[4];
        #pragma unroll
        for (int i = 0; i < 4; i++) {
            float rm = fmaxf(fmaxf(s[i][0], s[i][1]), fmaxf(s[i][2], s[i][3]));
            #pragma unroll
            for (int x = 1; x < 16; x <<= 1)
                rm = fmaxf(rm, __shfl_xor_sync(0xffffffffu, rm, x));
            float mnew = fmaxf(m[i], rm);
            alpha[i] = __expf(m[i] - mnew);
            m[i] = mnew;
            float rs = 0.f;
            #pragma unroll
            for (int j = 0; j < 4; j++) {
                s[i][j] = __expf(s[i][j] - mnew);
                rs += s[i][j];
            }
            #pragma unroll
            for (int x = 1; x < 16; x <<= 1)
                rs += __shfl_xor_sync(0xffffffffu, rs, x);
            l[i] = l[i] * alpha[i] + rs;
            #pragma unroll
            for (int j = 0; j < 4; j++) o[i][j] *= alpha[i];
        }
        // Store P transposed: Ps[j][q] (aliases Kt)
        #pragma unroll
        for (int j = 0; j < 4; j++)
            #pragma unroll
            for (int i = 0; i < 4; i++)
                Kt[(tx*4 + j)*SST + ty*4 + i] = s[i][j];
        __syncthreads();

        // O += P V : rows q=ty*4+ii, cols d=tx*4+cc
        #pragma unroll 8
        for (int j = 0; j < 64; j++) {
            float4 a4 = *reinterpret_cast<const float4*>(&Kt[j*SST + ty*4]);
            float4 b4 = *reinterpret_cast<const float4*>(&Vs[j*SST + tx*4]);
            const float a[4] = {a4.x, a4.y, a4.z, a4.w};
            const float bb[4] = {b4.x, b4.y, b4.z, b4.w};
            #pragma unroll
            for (int i = 0; i < 4; i++)
                #pragma unroll
                for (int c = 0; c < 4; c++)
                    o[i][c] += a[i] * bb[c];
        }
    }

    // Write O (merged heads): rows q, cols h*64 + tx*4..
    #pragma unroll
    for (int i = 0; i < 4; i++) {
        float inv = 1.f / l[i];
        int q = qt + ty*4 + i;
        float4 v;
        v.x = o[i][0]*inv; v.y = o[i][1]*inv; v.z = o[i][2]*inv; v.w = o[i][3]*inv;
        *reinterpret_cast<float4*>(
            &O[((size_t)b*Tq + q) * Cq + h*HDq + tx*4]) = v;
    }
}

// ---------------------------------------------------------------------------
// Launch
// ---------------------------------------------------------------------------
extern "C" void kernel_launch(void* const* d_in, const int* in_sizes, int n_in,
                              void* d_out, int out_size)
{
    (void)in_sizes; (void)n_in; (void)out_size;
    const float* queries = (const float*)d_in[0];
    const float* keys    = (const float*)d_in[1];
    const float* values  = (const float*)d_in[2];
    const float* Wq = (const float*)d_in[3];
    const float* bq = (const float*)d_in[4];
    const float* Wk = (const float*)d_in[5];
    const float* bk = (const float*)d_in[6];
    const float* Wv = (const float*)d_in[7];
    const float* bv = (const float*)d_in[8];
    const float* Wo = (const float*)d_in[9];
    const float* bo = (const float*)d_in[10];
    float* out = (float*)d_out;

    float *pQ, *pK, *pV, *pO;
    cudaGetSymbolAddress((void**)&pQ, g_Qd);
    cudaGetSymbolAddress((void**)&pK, g_Kd);
    cudaGetSymbolAddress((void**)&pV, g_V);
    cudaGetSymbolAddress((void**)&pO, g_O);

    cudaFuncSetAttribute(attn_kernel, cudaFuncAttributeMaxDynamicSharedMemorySize, ATT_SMEM);

    dim3 gg(Cq/64, Mq/64);             // (16, 64)
    proj_gemm<2><<<gg, 256>>>(queries, Wq, bq, pQ);   // Q d-major
    proj_gemm<2><<<gg, 256>>>(keys,    Wk, bk, pK);   // K d-major
    proj_gemm<1><<<gg, 256>>>(values,  Wv, bv, pV);   // V t-major

    dim3 ga(Tq/64, Hq, Bq);            // (32, 16, 2)
    attn_kernel<<<ga, 256, ATT_SMEM>>>(pQ, pK, pV, pO);

    proj_gemm<0><<<gg, 256>>>(pO, Wo, bo, out);
}

// round 7
// speedup vs baseline: 2.0604x; 1.1073x over previous
#include <cuda_runtime.h>
#include <cuda_bf16.h>
#include <math.h>
#include <stdint.h>

// Problem constants
#define Bq 2
#define Tq 2048
#define Cq 1024
#define Hq 16
#define HDq 64
#define Mq (Bq*Tq)          // 4096

// ---------------------------------------------------------------------------
// Device-global scratch (no allocation allowed)
// ---------------------------------------------------------------------------
__device__ float g_Qd[(size_t)Bq*Hq*HDq*Tq];  // [B,H,HD,T]  (d-major)
__device__ float g_Kd[(size_t)Bq*Hq*HDq*Tq];  // [B,H,HD,T]  (d-major)
__device__ float g_V [(size_t)Bq*Hq*Tq*HDq];  // [B,H,T,HD]
__device__ float g_O [(size_t)Bq*Tq*Cq];      // merged heads [B,T,C]

// ---------------------------------------------------------------------------
// Tiled SGEMM: out = A[4096,1024] * W[1024,1024] + bias
// BM=BN=128, BK=16, 256 threads, split-8x8 thread tile (1 B/FMA).
// MODE 0: flat [M,C] ; MODE 1: [B,H,T,HD] ; MODE 2: [B,H,HD,T] (d-major)
// ---------------------------------------------------------------------------
#define AST 132   // floats per As row (transposed store, 2-way max conflict)
#define BST 128

template<int MODE>
__global__ __launch_bounds__(256)
void proj_gemm(const float* __restrict__ A, const float* __restrict__ W,
               const float* __restrict__ bias, float* __restrict__ out)
{
    __shared__ float As[16*AST];   // As[k][m]
    __shared__ float Bs[16*BST];   // Bs[k][n]

    const int tid = threadIdx.x;
    const int tx  = tid & 15;          // N: cols {tx*4, 64+tx*4}
    const int ty  = tid >> 4;          // M: rows {ty*4, 64+ty*4}
    const int bm  = blockIdx.y * 128;
    const int bn  = blockIdx.x * 128;

    float acc[8][8] = {};

    for (int k0 = 0; k0 < Cq; k0 += 16) {
        // A tile 128x16 -> As[k][m] (transposed), 2 float4/thread
        #pragma unroll
        for (int t = 0; t < 2; t++) {
            int idx = tid + t*256;
            int r = idx >> 2, c4 = idx & 3;
            float4 va = *reinterpret_cast<const float4*>(
                A + (size_t)(bm + r) * Cq + k0 + c4*4);
            As[(c4*4+0)*AST + r] = va.x;
            As[(c4*4+1)*AST + r] = va.y;
            As[(c4*4+2)*AST + r] = va.z;
            As[(c4*4+3)*AST + r] = va.w;
        }
        // B tile 16x128, 2 float4/thread
        #pragma unroll
        for (int t = 0; t < 2; t++) {
            int idx = tid + t*256;
            int r = idx >> 5, c4 = idx & 31;
            float4 vb = *reinterpret_cast<const float4*>(
                W + (size_t)(k0 + r) * Cq + bn + c4*4);
            *reinterpret_cast<float4*>(&Bs[r*BST + c4*4]) = vb;
        }
        __syncthreads();

        #pragma unroll
        for (int k = 0; k < 16; k++) {
            float4 a0 = *reinterpret_cast<const float4*>(&As[k*AST + ty*4]);
            float4 a1 = *reinterpret_cast<const float4*>(&As[k*AST + 64 + ty*4]);
            float4 b0 = *reinterpret_cast<const float4*>(&Bs[k*BST + tx*4]);
            float4 b1 = *reinterpret_cast<const float4*>(&Bs[k*BST + 64 + tx*4]);
            const float a[8] = {a0.x,a0.y,a0.z,a0.w, a1.x,a1.y,a1.z,a1.w};
            const float b[8] = {b0.x,b0.y,b0.z,b0.w, b1.x,b1.y,b1.z,b1.w};
            #pragma unroll
            for (int i = 0; i < 8; i++)
                #pragma unroll
                for (int j = 0; j < 8; j++)
                    acc[i][j] += a[i] * b[j];
        }
        __syncthreads();
    }

    // Epilogue
    #pragma unroll
    for (int i = 0; i < 8; i++) {
        int m = bm + ((i < 4) ? (ty*4 + i) : (64 + ty*4 + i - 4));
        int b = m >> 11;
        int t = m & (Tq - 1);
        #pragma unroll
        for (int j = 0; j < 8; j++) {
            int n = bn + ((j < 4) ? (tx*4 + j) : (64 + tx*4 + j - 4));
            float v = acc[i][j] + __ldg(&bias[n]);
            if (MODE == 0) {
                out[(size_t)m * Cq + n] = v;
            } else {
                int h = n >> 6, d = n & 63;
                if (MODE == 1)
                    out[(((size_t)(b*Hq + h) * Tq) + t) * HDq + d] = v;
                else
                    out[(((size_t)(b*Hq + h) * HDq) + d) * Tq + t] = v;
            }
        }
    }
}

// ---------------------------------------------------------------------------
// Flash attention: block = 128 q x full kv loop (tiles of 128 j), 256 threads.
// S-GEMM split-8x8 (1 B/FMA); P -> smem via swizzled STS.128; PV 8x4.
// Smem: Qs[d][q] + Kt[d][j] + Vs[j][d] + Ps[j][q(sw)] = 160 KB, 1 block/SM.
// ---------------------------------------------------------------------------
#define ATT_SMEM ((64*128 + 64*128 + 128*64 + 128*128)*4)

__global__ __launch_bounds__(256)
void attn_kernel(const float* __restrict__ Qd, const float* __restrict__ Kd,
                 const float* __restrict__ V, float* __restrict__ O)
{
    extern __shared__ char smraw[];
    float* Qs = reinterpret_cast<float*>(smraw);   // [d][q]  64 x 128
    float* Kt = Qs + 64*128;                       // [d][j]  64 x 128
    float* Vs = Kt + 64*128;                       // [j][d]  128 x 64
    float* Ps = Vs + 128*64;                       // [j][q]  128 x 128 (swizzled)

    const int tid = threadIdx.x;
    const int tx  = tid & 15;          // j: {tx*4, 64+tx*4} ; d: tx*4
    const int ty  = tid >> 4;          // q: {ty*4, 64+ty*4}
    const int qt  = blockIdx.x * 128;
    const int h   = blockIdx.y;
    const int b   = blockIdx.z;

    const size_t dmaj = ((size_t)(b*Hq + h) * HDq) * Tq;
    const float* Qb = Qd + dmaj;
    const float* Kb = Kd + dmaj;
    const float* Vb = V + ((size_t)(b*Hq + h) * Tq) * HDq;

    // Load Q tile [64d x 128q], scaled
    {
        const float scale = 0.125f;
        #pragma unroll
        for (int s = 0; s < 8; s++) {
            int idx = tid + s*256;
            int d = idx >> 5, c4 = idx & 31;
            float4 v = *reinterpret_cast<const float4*>(Qb + (size_t)d * Tq + qt + c4*4);
            v.x *= scale; v.y *= scale; v.z *= scale; v.w *= scale;
            *reinterpret_cast<float4*>(&Qs[d*128 + c4*4]) = v;
        }
    }

    float o[8][4] = {};
    float m[8], l[8];
    #pragma unroll
    for (int i = 0; i < 8; i++) { m[i] = -INFINITY; l[i] = 0.f; }

    for (int kt0 = 0; kt0 < Tq; kt0 += 128) {
        __syncthreads();   // prior PV reads of Kt/Vs/Ps done

        // K tile [64d x 128j], V tile [128j x 64d]
        #pragma unroll
        for (int s = 0; s < 8; s++) {
            int idx = tid + s*256;
            int r = idx >> 5, c4 = idx & 31;
            *reinterpret_cast<float4*>(&Kt[r*128 + c4*4]) =
                *reinterpret_cast<const float4*>(Kb + (size_t)r * Tq + kt0 + c4*4);
            int jr = idx >> 4, d4 = idx & 15;
            *reinterpret_cast<float4*>(&Vs[jr*64 + d4*4]) =
                *reinterpret_cast<const float4*>(Vb + (size_t)(kt0 + jr) * HDq + d4*4);
        }
        __syncthreads();

        // S = Q^T K : split-8x8
        float s[8][8] = {};
        #pragma unroll 8
        for (int c = 0; c < 64; c++) {
            float4 a0 = *reinterpret_cast<const float4*>(&Qs[c*128 + ty*4]);
            float4 a1 = *reinterpret_cast<const float4*>(&Qs[c*128 + 64 + ty*4]);
            float4 b0 = *reinterpret_cast<const float4*>(&Kt[c*128 + tx*4]);
            float4 b1 = *reinterpret_cast<const float4*>(&Kt[c*128 + 64 + tx*4]);
            const float a[8] = {a0.x,a0.y,a0.z,a0.w, a1.x,a1.y,a1.z,a1.w};
            const float bb[8] = {b0.x,b0.y,b0.z,b0.w, b1.x,b1.y,b1.z,b1.w};
            #pragma unroll
            for (int i = 0; i < 8; i++)
                #pragma unroll
                for (int j = 0; j < 8; j++)
                    s[i][j] += a[i] * bb[j];
        }

        // Online softmax per q row (reduce across 16 tx lanes)
        #pragma unroll
        for (int i = 0; i < 8; i++) {
            float rm = s[i][0];
            #pragma unroll
            for (int j = 1; j < 8; j++) rm = fmaxf(rm, s[i][j]);
            #pragma unroll
            for (int x = 1; x < 16; x <<= 1)
                rm = fmaxf(rm, __shfl_xor_sync(0xffffffffu, rm, x));
            float mnew = fmaxf(m[i], rm);
            float alpha = __expf(m[i] - mnew);
            m[i] = mnew;
            float rs = 0.f;
            #pragma unroll
            for (int j = 0; j < 8; j++) {
                s[i][j] = __expf(s[i][j] - mnew);
                rs += s[i][j];
            }
            #pragma unroll
            for (int x = 1; x < 16; x <<= 1)
                rs += __shfl_xor_sync(0xffffffffu, rs, x);
            l[i] = l[i] * alpha + rs;
            #pragma unroll
            for (int c = 0; c < 4; c++) o[i][c] *= alpha;
        }

        // Store P[j][q] with XOR swizzle: c4phys = c4 ^ ((j>>2)&7)
        #pragma unroll
        for (int jj = 0; jj < 8; jj++) {
            int j = (jj < 4) ? (tx*4 + jj) : (64 + tx*4 + jj - 4);
            int sw = (j >> 2) & 7;
            float4 lo = make_float4(s[0][jj], s[1][jj], s[2][jj], s[3][jj]);
            float4 hi = make_float4(s[4][jj], s[5][jj], s[6][jj], s[7][jj]);
            *reinterpret_cast<float4*>(&Ps[j*128 + (ty ^ sw)*4])      = lo;
            *reinterpret_cast<float4*>(&Ps[j*128 + 64 + (ty ^ sw)*4]) = hi;
        }
        __syncthreads();

        // O += P V : o[8 q][4 d]
        #pragma unroll 4
        for (int j = 0; j < 128; j++) {
            int sw = (j >> 2) & 7;
            float4 a0 = *reinterpret_cast<const float4*>(&Ps[j*128 + (ty ^ sw)*4]);
            float4 a1 = *reinterpret_cast<const float4*>(&Ps[j*128 + 64 + (ty ^ sw)*4]);
            float4 bv = *reinterpret_cast<const float4*>(&Vs[j*64 + tx*4]);
            const float a[8] = {a0.x,a0.y,a0.z,a0.w, a1.x,a1.y,a1.z,a1.w};
            const float bb[4] = {bv.x,bv.y,bv.z,bv.w};
            #pragma unroll
            for (int i = 0; i < 8; i++)
                #pragma unroll
                for (int c = 0; c < 4; c++)
                    o[i][c] += a[i] * bb[c];
        }
    }

    // Write O (merged heads)
    #pragma unroll
    for (int i = 0; i < 8; i++) {
        float inv = 1.f / l[i];
        int q = qt + ((i < 4) ? (ty*4 + i) : (64 + ty*4 + i - 4));
        float4 v;
        v.x = o[i][0]*inv; v.y = o[i][1]*inv; v.z = o[i][2]*inv; v.w = o[i][3]*inv;
        *reinterpret_cast<float4*>(
            &O[((size_t)b*Tq + q) * Cq + h*HDq + tx*4]) = v;
    }
}

// ---------------------------------------------------------------------------
// Launch
// ---------------------------------------------------------------------------
extern "C" void kernel_launch(void* const* d_in, const int* in_sizes, int n_in,
                              void* d_out, int out_size)
{
    (void)in_sizes; (void)n_in; (void)out_size;
    const float* queries = (const float*)d_in[0];
    const float* keys    = (const float*)d_in[1];
    const float* values  = (const float*)d_in[2];
    const float* Wq = (const float*)d_in[3];
    const float* bq = (const float*)d_in[4];
    const float* Wk = (const float*)d_in[5];
    const float* bk = (const float*)d_in[6];
    const float* Wv = (const float*)d_in[7];
    const float* bv = (const float*)d_in[8];
    const float* Wo = (const float*)d_in[9];
    const float* bo = (const float*)d_in[10];
    float* out = (float*)d_out;

    float *pQ, *pK, *pV, *pO;
    cudaGetSymbolAddress((void**)&pQ, g_Qd);
    cudaGetSymbolAddress((void**)&pK, g_Kd);
    cudaGetSymbolAddress((void**)&pV, g_V);
    cudaGetSymbolAddress((void**)&pO, g_O);

    cudaFuncSetAttribute(attn_kernel, cudaFuncAttributeMaxDynamicSharedMemorySize, ATT_SMEM);

    dim3 gg(Cq/128, Mq/128);           // (8, 32)
    proj_gemm<2><<<gg, 256>>>(queries, Wq, bq, pQ);   // Q d-major
    proj_gemm<2><<<gg, 256>>>(keys,    Wk, bk, pK);   // K d-major
    proj_gemm<1><<<gg, 256>>>(values,  Wv, bv, pV);   // V t-major

    dim3 ga(Tq/128, Hq, Bq);           // (16, 16, 2)
    attn_kernel<<<ga, 256, ATT_SMEM>>>(pQ, pK, pV, pO);

    proj_gemm<0><<<gg, 256>>>(pO, Wo, bo, out);
}

// round 8
// speedup vs baseline: 2.1513x; 1.0441x over previous
#include <cuda_runtime.h>
#include <cuda_bf16.h>
#include <math.h>
#include <stdint.h>

// Problem constants
#define Bq 2
#define Tq 2048
#define Cq 1024
#define Hq 16
#define HDq 64
#define Mq (Bq*Tq)          // 4096

// ---------------------------------------------------------------------------
// Device-global scratch
// ---------------------------------------------------------------------------
__device__ float g_Qd[(size_t)Bq*Hq*HDq*Tq];  // [B,H,HD,T]  (d-major)
__device__ float g_Kd[(size_t)Bq*Hq*HDq*Tq];  // [B,H,HD,T]  (d-major)
__device__ float g_V [(size_t)Bq*Hq*Tq*HDq];  // [B,H,T,HD]
__device__ float g_O [(size_t)Bq*Tq*Cq];      // merged heads [B,T,C]

// ---------------------------------------------------------------------------
// helpers
// ---------------------------------------------------------------------------
__device__ __forceinline__ uint32_t smem_u32(const void* p){
    uint32_t a;
    asm("{ .reg .u64 t; cvta.to.shared.u64 t, %1; cvt.u32.u64 %0, t; }"
        : "=r"(a) : "l"(p));
    return a;
}
__device__ __forceinline__ void cpa16(uint32_t s, const void* g){
    asm volatile("cp.async.cg.shared.global [%0], [%1], 16;" :: "r"(s), "l"(g));
}
__device__ __forceinline__ void cp_commit(){
    asm volatile("cp.async.commit_group;" ::: "memory");
}
template<int N>
__device__ __forceinline__ void cp_wait(){
    asm volatile("cp.async.wait_group %0;" :: "n"(N) : "memory");
}

// ---------------------------------------------------------------------------
// Tiled SGEMM: out = A[4096,1024] * W[1024,1024] + bias
// BM=BN=128, BK=16, 256 threads, split-8x8, 2-stage cp.async double buffer.
// A stored [m][k] (cp.async-direct); a-frags via broadcast LDS.32.
// MODE 0: flat [M,C] ; MODE 1: [B,H,T,HD] ; MODE 2: [B,H,HD,T] (d-major)
// ---------------------------------------------------------------------------
#define PG_ASZ (128*16)          // floats per A stage
#define PG_BSZ (16*128)          // floats per B stage
#define PG_STAGE (PG_ASZ + PG_BSZ)
#define PG_SMEM (2*PG_STAGE*4)   // 32KB

template<int MODE>
__global__ __launch_bounds__(256, 2)
void proj_gemm(const float* __restrict__ A, const float* __restrict__ W,
               const float* __restrict__ bias, float* __restrict__ out)
{
    extern __shared__ float psm[];
    const uint32_t sb = smem_u32(psm);

    const int tid = threadIdx.x;
    const int tx  = tid & 15;
    const int ty  = tid >> 4;
    const int bm  = blockIdx.y * 128;
    const int bn  = blockIdx.x * 128;

    // stage bases (bytes)
    const uint32_t aB[2] = { sb, sb + PG_STAGE*4 };
    const uint32_t bB[2] = { sb + PG_ASZ*4, sb + PG_STAGE*4 + PG_ASZ*4 };

    auto load_chunk = [&](int c) {
        int s = c & 1;
        int k0 = c * 16;
        #pragma unroll
        for (int t = 0; t < 2; t++) {
            int idx = tid + t*256;
            int r = idx >> 2, c4 = idx & 3;    // A: 128 rows x 4 chunks
            cpa16(aB[s] + (uint32_t)(r*64 + c4*16),
                  A + (size_t)(bm + r) * Cq + k0 + c4*4);
            int br = idx >> 5, bc = idx & 31;  // B: 16 rows x 32 chunks
            cpa16(bB[s] + (uint32_t)(br*512 + bc*16),
                  W + (size_t)(k0 + br) * Cq + bn + bc*4);
        }
    };

    float acc[8][8] = {};

    load_chunk(0);
    cp_commit();

    for (int c = 0; c < 64; c++) {
        if (c + 1 < 64) { load_chunk(c + 1); cp_commit(); cp_wait<1>(); }
        else            { cp_wait<0>(); }
        __syncthreads();

        const float* As = psm + (c & 1) * PG_STAGE;            // [m][k] rows 16f
        const float* Bs = psm + (c & 1) * PG_STAGE + PG_ASZ;   // [k][n] rows 128f
        #pragma unroll
        for (int k = 0; k < 16; k++) {
            float a[8], b[8];
            #pragma unroll
            for (int i = 0; i < 4; i++) {
                a[i]   = As[(ty*4 + i)*16 + k];
                a[4+i] = As[(64 + ty*4 + i)*16 + k];
            }
            float4 b0 = *reinterpret_cast<const float4*>(&Bs[k*128 + tx*4]);
            float4 b1 = *reinterpret_cast<const float4*>(&Bs[k*128 + 64 + tx*4]);
            b[0]=b0.x; b[1]=b0.y; b[2]=b0.z; b[3]=b0.w;
            b[4]=b1.x; b[5]=b1.y; b[6]=b1.z; b[7]=b1.w;
            #pragma unroll
            for (int i = 0; i < 8; i++)
                #pragma unroll
                for (int j = 0; j < 8; j++)
                    acc[i][j] += a[i] * b[j];
        }
        __syncthreads();
    }

    // Epilogue
    #pragma unroll
    for (int i = 0; i < 8; i++) {
        int m = bm + ((i < 4) ? (ty*4 + i) : (64 + ty*4 + i - 4));
        int b = m >> 11;
        int t = m & (Tq - 1);
        #pragma unroll
        for (int j = 0; j < 8; j++) {
            int n = bn + ((j < 4) ? (tx*4 + j) : (64 + tx*4 + j - 4));
            float v = acc[i][j] + __ldg(&bias[n]);
            if (MODE == 0) {
                out[(size_t)m * Cq + n] = v;
            } else {
                int h = n >> 6, d = n & 63;
                if (MODE == 1)
                    out[(((size_t)(b*Hq + h) * Tq) + t) * HDq + d] = v;
                else
                    out[(((size_t)(b*Hq + h) * HDq) + d) * Tq + t] = v;
            }
        }
    }
}

// ---------------------------------------------------------------------------
// Flash attention: 128q x (tiles of 128 j), 256 threads, split-8x8 S-GEMM,
// 2-stage cp.async K/V rings, exp2-domain softmax, swizzled Ps.
// Smem floats: Qs 8192 | Kt 2x8192 | Vs 2x8192 | Ps 16384  = 224 KB
// ---------------------------------------------------------------------------
#define QS_OFF   0
#define KT_OFF   8192
#define VS_OFF   24576
#define PS_OFF   40960
#define ATT_SMEM ((40960 + 16384)*4)   // 229376 B

__global__ __launch_bounds__(256)
void attn_kernel(const float* __restrict__ Qd, const float* __restrict__ Kd,
                 const float* __restrict__ V, float* __restrict__ O)
{
    extern __shared__ float sm[];
    float* Qs = sm + QS_OFF;
    float* Ps = sm + PS_OFF;
    const uint32_t sb = smem_u32(sm);
    const uint32_t ktB[2] = { sb + KT_OFF*4, sb + (KT_OFF + 8192)*4 };
    const uint32_t vsB[2] = { sb + VS_OFF*4, sb + (VS_OFF + 8192)*4 };

    const int tid = threadIdx.x;
    const int tx  = tid & 15;
    const int ty  = tid >> 4;
    const int qt  = blockIdx.x * 128;
    const int h   = blockIdx.y;
    const int b   = blockIdx.z;

    const size_t dmaj = ((size_t)(b*Hq + h) * HDq) * Tq;
    const float* Qb = Qd + dmaj;
    const float* Kb = Kd + dmaj;
    const float* Vb = V + ((size_t)(b*Hq + h) * Tq) * HDq;

    // Load Q tile [64d x 128q], scaled by 1/8 * log2(e)
    {
        const float qscale = 0.125f * 1.4426950408889634f;
        #pragma unroll
        for (int s = 0; s < 8; s++) {
            int idx = tid + s*256;
            int d = idx >> 5, c4 = idx & 31;
            float4 v = *reinterpret_cast<const float4*>(Qb + (size_t)d * Tq + qt + c4*4);
            v.x *= qscale; v.y *= qscale; v.z *= qscale; v.w *= qscale;
            *reinterpret_cast<float4*>(&Qs[d*128 + c4*4]) = v;
        }
    }

    auto cp_tile = [&](int t) {
        int s = t & 1;
        int kt0 = t * 128;
        #pragma unroll
        for (int u = 0; u < 8; u++) {
            int idx = tid + u*256;
            int r = idx >> 5, c4 = idx & 31;   // K: [64d][128j]
            cpa16(ktB[s] + (uint32_t)(r*512 + c4*16),
                  Kb + (size_t)r * Tq + kt0 + c4*4);
            int jr = idx >> 4, d4 = idx & 15;  // V: [128j][64d]
            cpa16(vsB[s] + (uint32_t)(jr*256 + d4*16),
                  Vb + (size_t)(kt0 + jr) * HDq + d4*4);
        }
    };

    float o[8][4] = {};
    float m[8], l[8];
    #pragma unroll
    for (int i = 0; i < 8; i++) { m[i] = -INFINITY; l[i] = 0.f; }

    const int sw  = tx & 7;               // constant store swizzle
    const int col = (ty ^ sw) * 4;

    cp_tile(0);
    cp_commit();

    for (int t = 0; t < Tq/128; t++) {
        if (t + 1 < Tq/128) { cp_tile(t + 1); cp_commit(); cp_wait<1>(); }
        else                { cp_wait<0>(); }
        __syncthreads();

        const float* Kt = sm + KT_OFF + (t & 1) * 8192;
        const float* Vs = sm + VS_OFF + (t & 1) * 8192;

        // S = Q^T K (log2 domain), split-8x8
        float s[8][8] = {};
        #pragma unroll 8
        for (int c = 0; c < 64; c++) {
            float4 a0 = *reinterpret_cast<const float4*>(&Qs[c*128 + ty*4]);
            float4 a1 = *reinterpret_cast<const float4*>(&Qs[c*128 + 64 + ty*4]);
            float4 b0 = *reinterpret_cast<const float4*>(&Kt[c*128 + tx*4]);
            float4 b1 = *reinterpret_cast<const float4*>(&Kt[c*128 + 64 + tx*4]);
            const float a[8] = {a0.x,a0.y,a0.z,a0.w, a1.x,a1.y,a1.z,a1.w};
            const float bb[8] = {b0.x,b0.y,b0.z,b0.w, b1.x,b1.y,b1.z,b1.w};
            #pragma unroll
            for (int i = 0; i < 8; i++)
                #pragma unroll
                for (int j = 0; j < 8; j++)
                    s[i][j] += a[i] * bb[j];
        }

        // Online softmax in exp2 domain
        #pragma unroll
        for (int i = 0; i < 8; i++) {
            float rm = s[i][0];
            #pragma unroll
            for (int j = 1; j < 8; j++) rm = fmaxf(rm, s[i][j]);
            #pragma unroll
            for (int x = 1; x < 16; x <<= 1)
                rm = fmaxf(rm, __shfl_xor_sync(0xffffffffu, rm, x));
            float mnew = fmaxf(m[i], rm);
            float alpha = exp2f(m[i] - mnew);
            m[i] = mnew;
            float rs = 0.f;
            #pragma unroll
            for (int j = 0; j < 8; j++) {
                s[i][j] = exp2f(s[i][j] - mnew);
                rs += s[i][j];
            }
            #pragma unroll
            for (int x = 1; x < 16; x <<= 1)
                rs += __shfl_xor_sync(0xffffffffu, rs, x);
            l[i] = l[i] * alpha + rs;
            #pragma unroll
            for (int c = 0; c < 4; c++) o[i][c] *= alpha;
        }

        // Store P[j][q] swizzled (conflict-free per phase: sw = tx&7)
        #pragma unroll
        for (int jj = 0; jj < 8; jj++) {
            int j = (jj < 4) ? (tx*4 + jj) : (64 + tx*4 + jj - 4);
            *reinterpret_cast<float4*>(&Ps[j*128 + col]) =
                make_float4(s[0][jj], s[1][jj], s[2][jj], s[3][jj]);
            *reinterpret_cast<float4*>(&Ps[j*128 + 64 + col]) =
                make_float4(s[4][jj], s[5][jj], s[6][jj], s[7][jj]);
        }
        __syncthreads();

        // O += P V  (jg-grouped: constant swizzle per group)
        #pragma unroll 2
        for (int jg = 0; jg < 32; jg++) {
            int rcol = (ty ^ (jg & 7)) * 4;
            const float* Pb = &Ps[jg*4*128];
            const float* Vbv = &Vs[jg*4*64 + tx*4];
            #pragma unroll
            for (int jj = 0; jj < 4; jj++) {
                float4 a0 = *reinterpret_cast<const float4*>(&Pb[jj*128 + rcol]);
                float4 a1 = *reinterpret_cast<const float4*>(&Pb[jj*128 + 64 + rcol]);
                float4 bv = *reinterpret_cast<const float4*>(&Vbv[jj*64]);
                const float a[8] = {a0.x,a0.y,a0.z,a0.w, a1.x,a1.y,a1.z,a1.w};
                const float bb[4] = {bv.x,bv.y,bv.z,bv.w};
                #pragma unroll
                for (int i = 0; i < 8; i++)
                    #pragma unroll
                    for (int c = 0; c < 4; c++)
                        o[i][c] += a[i] * bb[c];
            }
        }
        __syncthreads();
    }

    // Write O (merged heads)
    #pragma unroll
    for (int i = 0; i < 8; i++) {
        float inv = 1.f / l[i];
        int q = qt + ((i < 4) ? (ty*4 + i) : (64 + ty*4 + i - 4));
        float4 v;
        v.x = o[i][0]*inv; v.y = o[i][1]*inv; v.z = o[i][2]*inv; v.w = o[i][3]*inv;
        *reinterpret_cast<float4*>(
            &O[((size_t)b*Tq + q) * Cq + h*HDq + tx*4]) = v;
    }
}

// ---------------------------------------------------------------------------
// Launch
// ---------------------------------------------------------------------------
extern "C" void kernel_launch(void* const* d_in, const int* in_sizes, int n_in,
                              void* d_out, int out_size)
{
    (void)in_sizes; (void)n_in; (void)out_size;
    const float* queries = (const float*)d_in[0];
    const float* keys    = (const float*)d_in[1];
    const float* values  = (const float*)d_in[2];
    const float* Wq = (const float*)d_in[3];
    const float* bq = (const float*)d_in[4];
    const float* Wk = (const float*)d_in[5];
    const float* bk = (const float*)d_in[6];
    const float* Wv = (const float*)d_in[7];
    const float* bv = (const float*)d_in[8];
    const float* Wo = (const float*)d_in[9];
    const float* bo = (const float*)d_in[10];
    float* out = (float*)d_out;

    float *pQ, *pK, *pV, *pO;
    cudaGetSymbolAddress((void**)&pQ, g_Qd);
    cudaGetSymbolAddress((void**)&pK, g_Kd);
    cudaGetSymbolAddress((void**)&pV, g_V);
    cudaGetSymbolAddress((void**)&pO, g_O);

    cudaFuncSetAttribute(attn_kernel, cudaFuncAttributeMaxDynamicSharedMemorySize, ATT_SMEM);
    cudaFuncSetAttribute(proj_gemm<0>, cudaFuncAttributeMaxDynamicSharedMemorySize, PG_SMEM);
    cudaFuncSetAttribute(proj_gemm<1>, cudaFuncAttributeMaxDynamicSharedMemorySize, PG_SMEM);
    cudaFuncSetAttribute(proj_gemm<2>, cudaFuncAttributeMaxDynamicSharedMemorySize, PG_SMEM);

    dim3 gg(Cq/128, Mq/128);           // (8, 32)
    proj_gemm<2><<<gg, 256, PG_SMEM>>>(queries, Wq, bq, pQ);   // Q d-major
    proj_gemm<2><<<gg, 256, PG_SMEM>>>(keys,    Wk, bk, pK);   // K d-major
    proj_gemm<1><<<gg, 256, PG_SMEM>>>(values,  Wv, bv, pV);   // V t-major

    dim3 ga(Tq/128, Hq, Bq);           // (16, 16, 2)
    attn_kernel<<<ga, 256, ATT_SMEM>>>(pQ, pK, pV, pO);

    proj_gemm<0><<<gg, 256, PG_SMEM>>>(pO, Wo, bo, out);
}

// round 9
// speedup vs baseline: 2.1567x; 1.0025x over previous
#include <cuda_runtime.h>
#include <cuda_bf16.h>
#include <math.h>
#include <stdint.h>

// Problem constants
#define Bq 2
#define Tq 2048
#define Cq 1024
#define Hq 16
#define HDq 64
#define Mq (Bq*Tq)          // 4096

// ---------------------------------------------------------------------------
// Device-global scratch
// ---------------------------------------------------------------------------
__device__ float g_Qd[(size_t)Bq*Hq*HDq*Tq];  // [B,H,HD,T]  (d-major)
__device__ float g_Kd[(size_t)Bq*Hq*HDq*Tq];  // [B,H,HD,T]  (d-major)
__device__ float g_V [(size_t)Bq*Hq*Tq*HDq];  // [B,H,T,HD]
__device__ float g_O [(size_t)Bq*Tq*Cq];      // merged heads [B,T,C]

// ---------------------------------------------------------------------------
// helpers
// ---------------------------------------------------------------------------
__device__ __forceinline__ uint32_t smem_u32(const void* p){
    uint32_t a;
    asm("{ .reg .u64 t; cvta.to.shared.u64 t, %1; cvt.u32.u64 %0, t; }"
        : "=r"(a) : "l"(p));
    return a;
}
__device__ __forceinline__ void cpa16(uint32_t s, const void* g){
    asm volatile("cp.async.cg.shared.global [%0], [%1], 16;" :: "r"(s), "l"(g));
}
__device__ __forceinline__ void cp_commit(){
    asm volatile("cp.async.commit_group;" ::: "memory");
}
template<int N>
__device__ __forceinline__ void cp_wait(){
    asm volatile("cp.async.wait_group %0;" :: "n"(N) : "memory");
}
__device__ __forceinline__ float ex2(float x){
    float y; asm("ex2.approx.ftz.f32 %0, %1;" : "=f"(y) : "f"(x)); return y;
}

// ---------------------------------------------------------------------------
// Tiled SGEMM: out = A[4096,1024] * W[1024,1024] + bias
// BM=BN=128, BK=16, 256 threads, split-8x8, 2 CTAs/SM.
// A: LDG (2 chunks ahead) -> STS transposed As[k][m] -> a-frags 2x LDS.128.
// B: cp.async double-buffered. ONE barrier per chunk.
// MODE 0: flat [M,C] ; MODE 1: [B,H,T,HD] ; MODE 2: [B,H,HD,T] (d-major)
// ---------------------------------------------------------------------------
#define AST 132
#define PG_AS (16*AST)           // floats per A stage
#define PG_BS (16*128)           // floats per B stage
#define PG_SMEM ((2*PG_AS + 2*PG_BS)*4)   // 33280 B

template<int MODE>
__global__ __launch_bounds__(256, 2)
void proj_gemm(const float* __restrict__ A, const float* __restrict__ W,
               const float* __restrict__ bias, float* __restrict__ out)
{
    extern __shared__ float psm[];
    float* Asm = psm;                 // 2 stages [16][AST]
    float* Bsm = psm + 2*PG_AS;       // 2 stages [16][128]
    const uint32_t bsb = smem_u32(Bsm);

    const int tid = threadIdx.x;
    const int tx  = tid & 15;
    const int ty  = tid >> 4;
    const int bm  = blockIdx.y * 128;
    const int bn  = blockIdx.x * 128;
    const int rr0 = tid >> 2, cc0 = tid & 3;   // A load/stage coords

    float4 rA[2];
    auto ldgA = [&](int c) {
        int k0 = c * 16;
        #pragma unroll
        for (int t = 0; t < 2; t++) {
            int rr = rr0 + t*64;
            rA[t] = *reinterpret_cast<const float4*>(
                A + (size_t)(bm + rr) * Cq + k0 + cc0*4);
        }
    };
    auto stsA = [&](int c) {
        float* dst = Asm + (c & 1) * PG_AS;
        #pragma unroll
        for (int t = 0; t < 2; t++) {
            int rr = rr0 + t*64;
            dst[(cc0*4+0)*AST + rr] = rA[t].x;
            dst[(cc0*4+1)*AST + rr] = rA[t].y;
            dst[(cc0*4+2)*AST + rr] = rA[t].z;
            dst[(cc0*4+3)*AST + rr] = rA[t].w;
        }
    };
    auto cpB = [&](int c) {
        int s = c & 1, k0 = c * 16;
        #pragma unroll
        for (int t = 0; t < 2; t++) {
            int idx = tid + t*256;
            int br = idx >> 5, bc = idx & 31;
            cpa16(bsb + (uint32_t)(s*PG_BS + br*128 + bc*4)*4,
                  W + (size_t)(k0 + br) * Cq + bn + bc*4);
        }
    };

    float acc[8][8] = {};

    // prologue: stage chunk 0, prefetch A(1)
    ldgA(0); stsA(0);
    cpB(0); cp_commit();
    ldgA(1);
    cp_wait<0>();
    __syncthreads();

    for (int c = 0; c < 64; c++) {
        // stage ^1 is free (compute c-1 ended at last barrier)
        if (c + 1 < 64) { cpB(c + 1); cp_commit(); stsA(c + 1); }
        if (c + 2 < 64) ldgA(c + 2);

        const float* As = Asm + (c & 1) * PG_AS;
        const float* Bs = Bsm + (c & 1) * PG_BS;
        #pragma unroll
        for (int k = 0; k < 16; k++) {
            float4 a0 = *reinterpret_cast<const float4*>(&As[k*AST + ty*4]);
            float4 a1 = *reinterpret_cast<const float4*>(&As[k*AST + 64 + ty*4]);
            float4 b0 = *reinterpret_cast<const float4*>(&Bs[k*128 + tx*4]);
            float4 b1 = *reinterpret_cast<const float4*>(&Bs[k*128 + 64 + tx*4]);
            const float a[8] = {a0.x,a0.y,a0.z,a0.w, a1.x,a1.y,a1.z,a1.w};
            const float b[8] = {b0.x,b0.y,b0.z,b0.w, b1.x,b1.y,b1.z,b1.w};
            #pragma unroll
            for (int i = 0; i < 8; i++)
                #pragma unroll
                for (int j = 0; j < 8; j++)
                    acc[i][j] += a[i] * b[j];
        }
        cp_wait<0>();
        __syncthreads();
    }

    // Epilogue
    #pragma unroll
    for (int i = 0; i < 8; i++) {
        int m = bm + ((i < 4) ? (ty*4 + i) : (64 + ty*4 + i - 4));
        int b = m >> 11;
        int t = m & (Tq - 1);
        #pragma unroll
        for (int j = 0; j < 8; j++) {
            int n = bn + ((j < 4) ? (tx*4 + j) : (64 + tx*4 + j - 4));
            float v = acc[i][j] + __ldg(&bias[n]);
            if (MODE == 0) {
                out[(size_t)m * Cq + n] = v;
            } else {
                int h = n >> 6, d = n & 63;
                if (MODE == 1)
                    out[(((size_t)(b*Hq + h) * Tq) + t) * HDq + d] = v;
                else
                    out[(((size_t)(b*Hq + h) * HDq) + d) * Tq + t] = v;
            }
        }
    }
}

// ---------------------------------------------------------------------------
// Flash attention: block = 64 q x (tiles of 128 j), 256 threads, 4q x 8j
// per thread. Smem 112 KB -> 2 CTAs/SM (16 warps). Single-buffer K/V with
// cp.async issued immediately after the freeing barrier. 3 barriers/tile.
// Layout (floats): Qs[64d][64q] | Kt[64d][128j] | Vs[128j][64d] | Ps[128j][64q]
// ---------------------------------------------------------------------------
#define ATT_SMEM ((4096 + 8192 + 8192 + 8192)*4)   // 114688 B

__global__ __launch_bounds__(256, 2)
void attn_kernel(const float* __restrict__ Qd, const float* __restrict__ Kd,
                 const float* __restrict__ V, float* __restrict__ O)
{
    extern __shared__ float sm[];
    float* Qs = sm;            // [64][64]
    float* Kt = sm + 4096;     // [64][128]
    float* Vs = sm + 12288;    // [128][64]
    float* Ps = sm + 20480;    // [128][64] xor-swizzled
    const uint32_t ktb = smem_u32(Kt);
    const uint32_t vsb = smem_u32(Vs);

    const int tid = threadIdx.x;
    const int tx  = tid & 15;          // j: {tx*4, 64+tx*4}
    const int ty  = tid >> 4;          // q: ty*4..+3
    const int qt  = blockIdx.x * 64;
    const int h   = blockIdx.y;
    const int b   = blockIdx.z;

    const size_t dmaj = ((size_t)(b*Hq + h) * HDq) * Tq;
    const float* Qb = Qd + dmaj;
    const float* Kb = Kd + dmaj;
    const float* Vb = V + ((size_t)(b*Hq + h) * Tq) * HDq;

    auto cpK = [&](int t) {            // Kt[d][j] <- Kd rows (contiguous)
        int kt0 = t * 128;
        #pragma unroll
        for (int u = 0; u < 8; u++) {
            int idx = tid + u*256;
            int r = idx >> 5, c = idx & 31;
            cpa16(ktb + (uint32_t)(r*128 + c*4)*4, Kb + (size_t)r * Tq + kt0 + c*4);
        }
    };
    auto cpV = [&](int t) {            // Vs[j][d]
        int kt0 = t * 128;
        #pragma unroll
        for (int u = 0; u < 8; u++) {
            int idx = tid + u*256;
            int jr = idx >> 4, d4 = idx & 15;
            cpa16(vsb + (uint32_t)(jr*64 + d4*4)*4,
                  Vb + (size_t)(kt0 + jr) * HDq + d4*4);
        }
    };

    cpK(0); cp_commit();
    cpV(0); cp_commit();

    // Q tile [64d][64q], scaled by 1/8 * log2(e)
    {
        const float qscale = 0.125f * 1.4426950408889634f;
        #pragma unroll
        for (int u = 0; u < 4; u++) {
            int idx = tid + u*256;
            int d = idx >> 4, c4 = idx & 15;
            float4 v = *reinterpret_cast<const float4*>(Qb + (size_t)d * Tq + qt + c4*4);
            v.x *= qscale; v.y *= qscale; v.z *= qscale; v.w *= qscale;
            *reinterpret_cast<float4*>(&Qs[d*64 + c4*4]) = v;
        }
    }

    float o[4][4] = {};
    float m[4], l[4];
    #pragma unroll
    for (int i = 0; i < 4; i++) { m[i] = -INFINITY; l[i] = 0.f; }

    for (int t = 0; t < Tq/128; t++) {
        cp_wait<0>();
        __syncthreads();               // K/V(t) ready; all PV(t-1) done

        // S = Q^T K : s[4 q][8 j]
        float s[4][8] = {};
        #pragma unroll 8
        for (int c = 0; c < 64; c++) {
            float4 a4 = *reinterpret_cast<const float4*>(&Qs[c*64 + ty*4]);
            float4 b0 = *reinterpret_cast<const float4*>(&Kt[c*128 + tx*4]);
            float4 b1 = *reinterpret_cast<const float4*>(&Kt[c*128 + 64 + tx*4]);
            const float a[4] = {a4.x, a4.y, a4.z, a4.w};
            const float bb[8] = {b0.x,b0.y,b0.z,b0.w, b1.x,b1.y,b1.z,b1.w};
            #pragma unroll
            for (int i = 0; i < 4; i++)
                #pragma unroll
                for (int j = 0; j < 8; j++)
                    s[i][j] += a[i] * bb[j];
        }

        // Online softmax (exp2 domain), reduce across 16 tx lanes
        #pragma unroll
        for (int i = 0; i < 4; i++) {
            float rm = s[i][0];
            #pragma unroll
            for (int j = 1; j < 8; j++) rm = fmaxf(rm, s[i][j]);
            #pragma unroll
            for (int x = 1; x < 16; x <<= 1)
                rm = fmaxf(rm, __shfl_xor_sync(0xffffffffu, rm, x));
            float mnew = fmaxf(m[i], rm);
            float alpha = ex2(m[i] - mnew);
            m[i] = mnew;
            float rs = 0.f;
            #pragma unroll
            for (int j = 0; j < 8; j++) {
                s[i][j] = ex2(s[i][j] - mnew);
                rs += s[i][j];
            }
            #pragma unroll
            for (int x = 1; x < 16; x <<= 1)
                rs += __shfl_xor_sync(0xffffffffu, rs, x);
            l[i] = l[i] * alpha + rs;
            #pragma unroll
            for (int c = 0; c < 4; c++) o[i][c] *= alpha;
        }

        // Store P[j][q] xor-swizzled (safe: PV(t-1) ended before top barrier)
        #pragma unroll
        for (int jj = 0; jj < 8; jj++) {
            int j = (jj < 4) ? (tx*4 + jj) : (64 + tx*4 + jj - 4);
            int col = ((ty ^ (j & 15)) << 2);
            *reinterpret_cast<float4*>(&Ps[j*64 + col]) =
                make_float4(s[0][jj], s[1][jj], s[2][jj], s[3][jj]);
        }
        __syncthreads();               // Kt free for next load; P visible

        if (t + 1 < Tq/128) { cpK(t + 1); cp_commit(); }

        // O += P V : o[4 q][4 d]
        #pragma unroll 4
        for (int j = 0; j < 128; j++) {
            int col = ((ty ^ (j & 15)) << 2);
            float4 a4 = *reinterpret_cast<const float4*>(&Ps[j*64 + col]);
            float4 v4 = *reinterpret_cast<const float4*>(&Vs[j*64 + tx*4]);
            const float a[4] = {a4.x, a4.y, a4.z, a4.w};
            const float bb[4] = {v4.x, v4.y, v4.z, v4.w};
            #pragma unroll
            for (int i = 0; i < 4; i++)
                #pragma unroll
                for (int c = 0; c < 4; c++)
                    o[i][c] += a[i] * bb[c];
        }
        __syncthreads();               // Vs free for next load

        if (t + 1 < Tq/128) { cpV(t + 1); cp_commit(); }
    }

    // Write O (merged heads)
    #pragma unroll
    for (int i = 0; i < 4; i++) {
        float inv = 1.f / l[i];
        int q = qt + ty*4 + i;
        float4 v;
        v.x = o[i][0]*inv; v.y = o[i][1]*inv; v.z = o[i][2]*inv; v.w = o[i][3]*inv;
        *reinterpret_cast<float4*>(
            &O[((size_t)b*Tq + q) * Cq + h*HDq + tx*4]) = v;
    }
}

// ---------------------------------------------------------------------------
// Launch
// ---------------------------------------------------------------------------
extern "C" void kernel_launch(void* const* d_in, const int* in_sizes, int n_in,
                              void* d_out, int out_size)
{
    (void)in_sizes; (void)n_in; (void)out_size;
    const float* queries = (const float*)d_in[0];
    const float* keys    = (const float*)d_in[1];
    const float* values  = (const float*)d_in[2];
    const float* Wq = (const float*)d_in[3];
    const float* bq = (const float*)d_in[4];
    const float* Wk = (const float*)d_in[5];
    const float* bk = (const float*)d_in[6];
    const float* Wv = (const float*)d_in[7];
    const float* bv = (const float*)d_in[8];
    const float* Wo = (const float*)d_in[9];
    const float* bo = (const float*)d_in[10];
    float* out = (float*)d_out;

    float *pQ, *pK, *pV, *pO;
    cudaGetSymbolAddress((void**)&pQ, g_Qd);
    cudaGetSymbolAddress((void**)&pK, g_Kd);
    cudaGetSymbolAddress((void**)&pV, g_V);
    cudaGetSymbolAddress((void**)&pO, g_O);

    cudaFuncSetAttribute(attn_kernel, cudaFuncAttributeMaxDynamicSharedMemorySize, ATT_SMEM);
    cudaFuncSetAttribute(proj_gemm<0>, cudaFuncAttributeMaxDynamicSharedMemorySize, PG_SMEM);
    cudaFuncSetAttribute(proj_gemm<1>, cudaFuncAttributeMaxDynamicSharedMemorySize, PG_SMEM);
    cudaFuncSetAttribute(proj_gemm<2>, cudaFuncAttributeMaxDynamicSharedMemorySize, PG_SMEM);

    dim3 gg(Cq/128, Mq/128);           // (8, 32)
    proj_gemm<2><<<gg, 256, PG_SMEM>>>(queries, Wq, bq, pQ);   // Q d-major
    proj_gemm<2><<<gg, 256, PG_SMEM>>>(keys,    Wk, bk, pK);   // K d-major
    proj_gemm<1><<<gg, 256, PG_SMEM>>>(values,  Wv, bv, pV);   // V t-major

    dim3 ga(Tq/64, Hq, Bq);            // (32, 16, 2)
    attn_kernel<<<ga, 256, ATT_SMEM>>>(pQ, pK, pV, pO);

    proj_gemm<0><<<gg, 256, PG_SMEM>>>(pO, Wo, bo, out);
}

// round 10
// speedup vs baseline: 2.2610x; 1.0483x over previous
#include <cuda_runtime.h>
#include <cuda_bf16.h>
#include <math.h>
#include <stdint.h>

// Problem constants
#define Bq 2
#define Tq 2048
#define Cq 1024
#define Hq 16
#define HDq 64
#define Mq (Bq*Tq)          // 4096

// ---------------------------------------------------------------------------
// Device-global scratch
// ---------------------------------------------------------------------------
__device__ float g_Qd[(size_t)Bq*Hq*HDq*Tq];  // [B,H,HD,T]  (d-major)
__device__ float g_Kd[(size_t)Bq*Hq*HDq*Tq];  // [B,H,HD,T]  (d-major)
__device__ float g_V [(size_t)Bq*Hq*Tq*HDq];  // [B,H,T,HD]
__device__ float g_O [(size_t)Bq*Tq*Cq];      // merged heads [B,T,C]

// ---------------------------------------------------------------------------
// helpers
// ---------------------------------------------------------------------------
__device__ __forceinline__ uint32_t smem_u32(const void* p){
    uint32_t a;
    asm("{ .reg .u64 t; cvta.to.shared.u64 t, %1; cvt.u32.u64 %0, t; }"
        : "=r"(a) : "l"(p));
    return a;
}
__device__ __forceinline__ void cpa16(uint32_t s, const void* g){
    asm volatile("cp.async.cg.shared.global [%0], [%1], 16;" :: "r"(s), "l"(g));
}
__device__ __forceinline__ void cp_commit(){
    asm volatile("cp.async.commit_group;" ::: "memory");
}
template<int N>
__device__ __forceinline__ void cp_wait(){
    asm volatile("cp.async.wait_group %0;" :: "n"(N) : "memory");
}
__device__ __forceinline__ float ex2(float x){
    float y; asm("ex2.approx.ftz.f32 %0, %1;" : "=f"(y) : "f"(x)); return y;
}

// ---------------------------------------------------------------------------
// Tiled SGEMM (unchanged from round 9): BM=BN=128, BK=16, 256 thr, 2 CTAs/SM.
// ---------------------------------------------------------------------------
#define AST 132
#define PG_AS (16*AST)
#define PG_BS (16*128)
#define PG_SMEM ((2*PG_AS + 2*PG_BS)*4)   // 33280 B

template<int MODE>
__global__ __launch_bounds__(256, 2)
void proj_gemm(const float* __restrict__ A, const float* __restrict__ W,
               const float* __restrict__ bias, float* __restrict__ out)
{
    extern __shared__ float psm[];
    float* Asm = psm;
    float* Bsm = psm + 2*PG_AS;
    const uint32_t bsb = smem_u32(Bsm);

    const int tid = threadIdx.x;
    const int tx  = tid & 15;
    const int ty  = tid >> 4;
    const int bm  = blockIdx.y * 128;
    const int bn  = blockIdx.x * 128;
    const int rr0 = tid >> 2, cc0 = tid & 3;

    float4 rA[2];
    auto ldgA = [&](int c) {
        int k0 = c * 16;
        #pragma unroll
        for (int t = 0; t < 2; t++) {
            int rr = rr0 + t*64;
            rA[t] = *reinterpret_cast<const float4*>(
                A + (size_t)(bm + rr) * Cq + k0 + cc0*4);
        }
    };
    auto stsA = [&](int c) {
        float* dst = Asm + (c & 1) * PG_AS;
        #pragma unroll
        for (int t = 0; t < 2; t++) {
            int rr = rr0 + t*64;
            dst[(cc0*4+0)*AST + rr] = rA[t].x;
            dst[(cc0*4+1)*AST + rr] = rA[t].y;
            dst[(cc0*4+2)*AST + rr] = rA[t].z;
            dst[(cc0*4+3)*AST + rr] = rA[t].w;
        }
    };
    auto cpB = [&](int c) {
        int s = c & 1, k0 = c * 16;
        #pragma unroll
        for (int t = 0; t < 2; t++) {
            int idx = tid + t*256;
            int br = idx >> 5, bc = idx & 31;
            cpa16(bsb + (uint32_t)(s*PG_BS + br*128 + bc*4)*4,
                  W + (size_t)(k0 + br) * Cq + bn + bc*4);
        }
    };

    float acc[8][8] = {};

    ldgA(0); stsA(0);
    cpB(0); cp_commit();
    ldgA(1);
    cp_wait<0>();
    __syncthreads();

    for (int c = 0; c < 64; c++) {
        if (c + 1 < 64) { cpB(c + 1); cp_commit(); stsA(c + 1); }
        if (c + 2 < 64) ldgA(c + 2);

        const float* As = Asm + (c & 1) * PG_AS;
        const float* Bs = Bsm + (c & 1) * PG_BS;
        #pragma unroll
        for (int k = 0; k < 16; k++) {
            float4 a0 = *reinterpret_cast<const float4*>(&As[k*AST + ty*4]);
            float4 a1 = *reinterpret_cast<const float4*>(&As[k*AST + 64 + ty*4]);
            float4 b0 = *reinterpret_cast<const float4*>(&Bs[k*128 + tx*4]);
            float4 b1 = *reinterpret_cast<const float4*>(&Bs[k*128 + 64 + tx*4]);
            const float a[8] = {a0.x,a0.y,a0.z,a0.w, a1.x,a1.y,a1.z,a1.w};
            const float b[8] = {b0.x,b0.y,b0.z,b0.w, b1.x,b1.y,b1.z,b1.w};
            #pragma unroll
            for (int i = 0; i < 8; i++)
                #pragma unroll
                for (int j = 0; j < 8; j++)
                    acc[i][j] += a[i] * b[j];
        }
        cp_wait<0>();
        __syncthreads();
    }

    #pragma unroll
    for (int i = 0; i < 8; i++) {
        int m = bm + ((i < 4) ? (ty*4 + i) : (64 + ty*4 + i - 4));
        int b = m >> 11;
        int t = m & (Tq - 1);
        #pragma unroll
        for (int j = 0; j < 8; j++) {
            int n = bn + ((j < 4) ? (tx*4 + j) : (64 + tx*4 + j - 4));
            float v = acc[i][j] + __ldg(&bias[n]);
            if (MODE == 0) {
                out[(size_t)m * Cq + n] = v;
            } else {
                int h = n >> 6, d = n & 63;
                if (MODE == 1)
                    out[(((size_t)(b*Hq + h) * Tq) + t) * HDq + d] = v;
                else
                    out[(((size_t)(b*Hq + h) * HDq) + d) * Tq + t] = v;
            }
        }
    }
}

// ---------------------------------------------------------------------------
// Flash attention v3: block = 128 q x (tiles of 64 j), 256 threads,
// thread tile 8q x 4j. Smem 96 KB -> 2 CTAs/SM. exp2 softmax.
// Layout (floats): Qs[64d][128q] | Kt[64d][64j] | Vs[64j][64d] | Ps[64j][128q]
// ---------------------------------------------------------------------------
#define ATT_SMEM ((8192 + 4096 + 4096 + 8192)*4)   // 98304 B

__global__ __launch_bounds__(256, 2)
void attn_kernel(const float* __restrict__ Qd, const float* __restrict__ Kd,
                 const float* __restrict__ V, float* __restrict__ O)
{
    extern __shared__ float sm[];
    float* Qs = sm;            // [64][128]
    float* Kt = sm + 8192;     // [64][64]
    float* Vs = sm + 12288;    // [64][64]
    float* Ps = sm + 16384;    // [64][128] xor-swizzled cols
    const uint32_t ktb = smem_u32(Kt);
    const uint32_t vsb = smem_u32(Vs);

    const int tid = threadIdx.x;
    const int tx  = tid & 15;          // j: tx*4..+3
    const int ty  = tid >> 4;          // q: {ty*4, 64+ty*4}
    const int qt  = blockIdx.x * 128;
    const int h   = blockIdx.y;
    const int b   = blockIdx.z;

    const size_t dmaj = ((size_t)(b*Hq + h) * HDq) * Tq;
    const float* Qb = Qd + dmaj;
    const float* Kb = Kd + dmaj;
    const float* Vb = V + ((size_t)(b*Hq + h) * Tq) * HDq;

    auto cpK = [&](int t) {            // Kt[64d][64j]
        int kt0 = t * 64;
        #pragma unroll
        for (int u = 0; u < 4; u++) {
            int idx = tid + u*256;
            int r = idx >> 4, c = idx & 15;
            cpa16(ktb + (uint32_t)(r*64 + c*4)*4, Kb + (size_t)r * Tq + kt0 + c*4);
        }
    };
    auto cpV = [&](int t) {            // Vs[64j][64d]
        int kt0 = t * 64;
        #pragma unroll
        for (int u = 0; u < 4; u++) {
            int idx = tid + u*256;
            int jr = idx >> 4, d4 = idx & 15;
            cpa16(vsb + (uint32_t)(jr*64 + d4*4)*4,
                  Vb + (size_t)(kt0 + jr) * HDq + d4*4);
        }
    };

    cpK(0); cp_commit();
    cpV(0); cp_commit();

    // Q tile [64d][128q], scaled by 1/8 * log2(e)
    {
        const float qscale = 0.125f * 1.4426950408889634f;
        #pragma unroll
        for (int u = 0; u < 8; u++) {
            int idx = tid + u*256;
            int d = idx >> 5, c4 = idx & 31;
            float4 v = *reinterpret_cast<const float4*>(Qb + (size_t)d * Tq + qt + c4*4);
            v.x *= qscale; v.y *= qscale; v.z *= qscale; v.w *= qscale;
            *reinterpret_cast<float4*>(&Qs[d*128 + c4*4]) = v;
        }
    }

    float o[8][4] = {};
    float m[8], l[8];
    #pragma unroll
    for (int i = 0; i < 8; i++) { m[i] = -INFINITY; l[i] = 0.f; }

    const int ssw  = tx & 7;               // thread-constant store swizzle
    const int scol = (ty ^ ssw) << 2;

    for (int t = 0; t < Tq/64; t++) {
        cp_wait<0>();
        __syncthreads();               // K/V(t) ready; PV(t-1) done

        // S = Q^T K : s[8 q][4 j]
        float s[8][4] = {};
        #pragma unroll 8
        for (int c = 0; c < 64; c++) {
            float4 a0 = *reinterpret_cast<const float4*>(&Qs[c*128 + ty*4]);
            float4 a1 = *reinterpret_cast<const float4*>(&Qs[c*128 + 64 + ty*4]);
            float4 b4 = *reinterpret_cast<const float4*>(&Kt[c*64 + tx*4]);
            const float a[8] = {a0.x,a0.y,a0.z,a0.w, a1.x,a1.y,a1.z,a1.w};
            const float bb[4] = {b4.x, b4.y, b4.z, b4.w};
            #pragma unroll
            for (int i = 0; i < 8; i++)
                #pragma unroll
                for (int j = 0; j < 4; j++)
                    s[i][j] += a[i] * bb[j];
        }

        // Online softmax (exp2 domain), reduce across 16 tx lanes
        #pragma unroll
        for (int i = 0; i < 8; i++) {
            float rm = fmaxf(fmaxf(s[i][0], s[i][1]), fmaxf(s[i][2], s[i][3]));
            #pragma unroll
            for (int x = 1; x < 16; x <<= 1)
                rm = fmaxf(rm, __shfl_xor_sync(0xffffffffu, rm, x));
            float mnew = fmaxf(m[i], rm);
            float alpha = ex2(m[i] - mnew);
            m[i] = mnew;
            float rs = 0.f;
            #pragma unroll
            for (int j = 0; j < 4; j++) {
                s[i][j] = ex2(s[i][j] - mnew);
                rs += s[i][j];
            }
            #pragma unroll
            for (int x = 1; x < 16; x <<= 1)
                rs += __shfl_xor_sync(0xffffffffu, rs, x);
            l[i] = l[i] * alpha + rs;
            #pragma unroll
            for (int c = 0; c < 4; c++) o[i][c] *= alpha;
        }

        // Store P[j][q] swizzled: physical col = (ty ^ (j>>2 & 7))*4
        #pragma unroll
        for (int jj = 0; jj < 4; jj++) {
            int j = tx*4 + jj;
            *reinterpret_cast<float4*>(&Ps[j*128 + scol]) =
                make_float4(s[0][jj], s[1][jj], s[2][jj], s[3][jj]);
            *reinterpret_cast<float4*>(&Ps[j*128 + 64 + scol]) =
                make_float4(s[4][jj], s[5][jj], s[6][jj], s[7][jj]);
        }
        __syncthreads();               // Kt free; P visible

        if (t + 1 < Tq/64) { cpK(t + 1); cp_commit(); }

        // O += P V : o[8 q][4 d], swizzle hoisted per 4-j group
        #pragma unroll 2
        for (int jg = 0; jg < 16; jg++) {
            const int rcol = ((ty ^ (jg & 7)) << 2);
            const float* Pb  = &Ps[jg*4*128];
            const float* Vbv = &Vs[jg*4*64 + tx*4];
            #pragma unroll
            for (int jj = 0; jj < 4; jj++) {
                float4 a0 = *reinterpret_cast<const float4*>(&Pb[jj*128 + rcol]);
                float4 a1 = *reinterpret_cast<const float4*>(&Pb[jj*128 + 64 + rcol]);
                float4 v4 = *reinterpret_cast<const float4*>(&Vbv[jj*64]);
                const float a[8] = {a0.x,a0.y,a0.z,a0.w, a1.x,a1.y,a1.z,a1.w};
                const float bb[4] = {v4.x, v4.y, v4.z, v4.w};
                #pragma unroll
                for (int i = 0; i < 8; i++)
                    #pragma unroll
                    for (int c = 0; c < 4; c++)
                        o[i][c] += a[i] * bb[c];
            }
        }
        __syncthreads();               // Vs free

        if (t + 1 < Tq/64) { cpV(t + 1); cp_commit(); }
    }

    // Write O (merged heads)
    #pragma unroll
    for (int i = 0; i < 8; i++) {
        float inv = 1.f / l[i];
        int q = qt + ((i < 4) ? (ty*4 + i) : (64 + ty*4 + i - 4));
        float4 v;
        v.x = o[i][0]*inv; v.y = o[i][1]*inv; v.z = o[i][2]*inv; v.w = o[i][3]*inv;
        *reinterpret_cast<float4*>(
            &O[((size_t)b*Tq + q) * Cq + h*HDq + tx*4]) = v;
    }
}

// ---------------------------------------------------------------------------
// Launch
// ---------------------------------------------------------------------------
extern "C" void kernel_launch(void* const* d_in, const int* in_sizes, int n_in,
                              void* d_out, int out_size)
{
    (void)in_sizes; (void)n_in; (void)out_size;
    const float* queries = (const float*)d_in[0];
    const float* keys    = (const float*)d_in[1];
    const float* values  = (const float*)d_in[2];
    const float* Wq = (const float*)d_in[3];
    const float* bq = (const float*)d_in[4];
    const float* Wk = (const float*)d_in[5];
    const float* bk = (const float*)d_in[6];
    const float* Wv = (const float*)d_in[7];
    const float* bv = (const float*)d_in[8];
    const float* Wo = (const float*)d_in[9];
    const float* bo = (const float*)d_in[10];
    float* out = (float*)d_out;

    float *pQ, *pK, *pV, *pO;
    cudaGetSymbolAddress((void**)&pQ, g_Qd);
    cudaGetSymbolAddress((void**)&pK, g_Kd);
    cudaGetSymbolAddress((void**)&pV, g_V);
    cudaGetSymbolAddress((void**)&pO, g_O);

    cudaFuncSetAttribute(attn_kernel, cudaFuncAttributeMaxDynamicSharedMemorySize, ATT_SMEM);
    cudaFuncSetAttribute(proj_gemm<0>, cudaFuncAttributeMaxDynamicSharedMemorySize, PG_SMEM);
    cudaFuncSetAttribute(proj_gemm<1>, cudaFuncAttributeMaxDynamicSharedMemorySize, PG_SMEM);
    cudaFuncSetAttribute(proj_gemm<2>, cudaFuncAttributeMaxDynamicSharedMemorySize, PG_SMEM);

    dim3 gg(Cq/128, Mq/128);           // (8, 32)
    proj_gemm<2><<<gg, 256, PG_SMEM>>>(queries, Wq, bq, pQ);   // Q d-major
    proj_gemm<2><<<gg, 256, PG_SMEM>>>(keys,    Wk, bk, pK);   // K d-major
    proj_gemm<1><<<gg, 256, PG_SMEM>>>(values,  Wv, bv, pV);   // V t-major

    dim3 ga(Tq/128, Hq, Bq);           // (16, 16, 2)
    attn_kernel<<<ga, 256, ATT_SMEM>>>(pQ, pK, pV, pO);

    proj_gemm<0><<<gg, 256, PG_SMEM>>>(pO, Wo, bo, out);
}

// round 11
// speedup vs baseline: 2.2955x; 1.0153x over previous
#include <cuda_runtime.h>
#include <cuda_bf16.h>
#include <math.h>
#include <stdint.h>

// Problem constants
#define Bq 2
#define Tq 2048
#define Cq 1024
#define Hq 16
#define HDq 64
#define Mq (Bq*Tq)          // 4096

// ---------------------------------------------------------------------------
// Device-global scratch
// ---------------------------------------------------------------------------
__device__ float g_Qd[(size_t)Bq*Hq*HDq*Tq];  // [B,H,HD,T]  (d-major)
__device__ float g_Kd[(size_t)Bq*Hq*HDq*Tq];  // [B,H,HD,T]  (d-major)
__device__ float g_V [(size_t)Bq*Hq*Tq*HDq];  // [B,H,T,HD]
__device__ float g_O [(size_t)Bq*Tq*Cq];      // merged heads [B,T,C]

// ---------------------------------------------------------------------------
// helpers
// ---------------------------------------------------------------------------
__device__ __forceinline__ uint32_t smem_u32(const void* p){
    uint32_t a;
    asm("{ .reg .u64 t; cvta.to.shared.u64 t, %1; cvt.u32.u64 %0, t; }"
        : "=r"(a) : "l"(p));
    return a;
}
__device__ __forceinline__ void cpa16(uint32_t s, const void* g){
    asm volatile("cp.async.cg.shared.global [%0], [%1], 16;" :: "r"(s), "l"(g));
}
__device__ __forceinline__ void cp_commit(){
    asm volatile("cp.async.commit_group;" ::: "memory");
}
template<int N>
__device__ __forceinline__ void cp_wait(){
    asm volatile("cp.async.wait_group %0;" :: "n"(N) : "memory");
}
__device__ __forceinline__ float ex2(float x){
    float y; asm("ex2.approx.ftz.f32 %0, %1;" : "=f"(y) : "f"(x)); return y;
}

// ---------------------------------------------------------------------------
// GEMM core (shared by fused-QKV and output projection)
// BM=BN=128, BK=16, 256 threads, split-8x8, 2 CTAs/SM.
// ---------------------------------------------------------------------------
#define AST 132
#define PG_AS (16*AST)
#define PG_BS (16*128)
#define PG_SMEM ((2*PG_AS + 2*PG_BS)*4)   // 33280 B

// MODE 0: flat [M,C] ; MODE 1: [B,H,T,HD] ; MODE 2: [B,H,HD,T] (d-major)
template<int MODE>
__device__ __forceinline__
void gemm_body(const float* __restrict__ A, const float* __restrict__ W,
               const float* __restrict__ bias, float* __restrict__ out,
               float* psm, int bm, int bn)
{
    float* Asm = psm;
    float* Bsm = psm + 2*PG_AS;
    const uint32_t bsb = smem_u32(Bsm);

    const int tid = threadIdx.x;
    const int tx  = tid & 15;
    const int ty  = tid >> 4;
    const int rr0 = tid >> 2, cc0 = tid & 3;

    float4 rA[2];
    auto ldgA = [&](int c) {
        int k0 = c * 16;
        #pragma unroll
        for (int t = 0; t < 2; t++) {
            int rr = rr0 + t*64;
            rA[t] = *reinterpret_cast<const float4*>(
                A + (size_t)(bm + rr) * Cq + k0 + cc0*4);
        }
    };
    auto stsA = [&](int c) {
        float* dst = Asm + (c & 1) * PG_AS;
        #pragma unroll
        for (int t = 0; t < 2; t++) {
            int rr = rr0 + t*64;
            dst[(cc0*4+0)*AST + rr] = rA[t].x;
            dst[(cc0*4+1)*AST + rr] = rA[t].y;
            dst[(cc0*4+2)*AST + rr] = rA[t].z;
            dst[(cc0*4+3)*AST + rr] = rA[t].w;
        }
    };
    auto cpB = [&](int c) {
        int s = c & 1, k0 = c * 16;
        #pragma unroll
        for (int t = 0; t < 2; t++) {
            int idx = tid + t*256;
            int br = idx >> 5, bc = idx & 31;
            cpa16(bsb + (uint32_t)(s*PG_BS + br*128 + bc*4)*4,
                  W + (size_t)(k0 + br) * Cq + bn + bc*4);
        }
    };

    float acc[8][8] = {};

    ldgA(0); stsA(0);
    cpB(0); cp_commit();
    ldgA(1);
    cp_wait<0>();
    __syncthreads();

    for (int c = 0; c < 64; c++) {
        if (c + 1 < 64) { cpB(c + 1); cp_commit(); stsA(c + 1); }
        if (c + 2 < 64) ldgA(c + 2);

        const float* As = Asm + (c & 1) * PG_AS;
        const float* Bs = Bsm + (c & 1) * PG_BS;
        #pragma unroll
        for (int k = 0; k < 16; k++) {
            float4 a0 = *reinterpret_cast<const float4*>(&As[k*AST + ty*4]);
            float4 a1 = *reinterpret_cast<const float4*>(&As[k*AST + 64 + ty*4]);
            float4 b0 = *reinterpret_cast<const float4*>(&Bs[k*128 + tx*4]);
            float4 b1 = *reinterpret_cast<const float4*>(&Bs[k*128 + 64 + tx*4]);
            const float a[8] = {a0.x,a0.y,a0.z,a0.w, a1.x,a1.y,a1.z,a1.w};
            const float b[8] = {b0.x,b0.y,b0.z,b0.w, b1.x,b1.y,b1.z,b1.w};
            #pragma unroll
            for (int i = 0; i < 8; i++)
                #pragma unroll
                for (int j = 0; j < 8; j++)
                    acc[i][j] += a[i] * b[j];
        }
        cp_wait<0>();
        __syncthreads();
    }

    #pragma unroll
    for (int i = 0; i < 8; i++) {
        int m = bm + ((i < 4) ? (ty*4 + i) : (64 + ty*4 + i - 4));
        int b = m >> 11;
        int t = m & (Tq - 1);
        #pragma unroll
        for (int j = 0; j < 8; j++) {
            int n = bn + ((j < 4) ? (tx*4 + j) : (64 + tx*4 + j - 4));
            float v = acc[i][j] + __ldg(&bias[n]);
            if (MODE == 0) {
                out[(size_t)m * Cq + n] = v;
            } else {
                int h = n >> 6, d = n & 63;
                if (MODE == 1)
                    out[(((size_t)(b*Hq + h) * Tq) + t) * HDq + d] = v;
                else
                    out[(((size_t)(b*Hq + h) * HDq) + d) * Tq + t] = v;
            }
        }
    }
}

// Fused QKV: grid.z selects {Q,K,V}. Q,K -> d-major (MODE 2), V -> MODE 1.
__global__ __launch_bounds__(256, 2)
void qkv_gemm(const float* __restrict__ Aq, const float* __restrict__ Ak,
              const float* __restrict__ Av,
              const float* __restrict__ Wq, const float* __restrict__ bq,
              const float* __restrict__ Wk, const float* __restrict__ bk,
              const float* __restrict__ Wv, const float* __restrict__ bv,
              float* __restrict__ oq, float* __restrict__ ok,
              float* __restrict__ ov)
{
    extern __shared__ float psm[];
    const int bm = blockIdx.y * 128, bn = blockIdx.x * 128;
    const int z = blockIdx.z;
    if (z == 0)      gemm_body<2>(Aq, Wq, bq, oq, psm, bm, bn);
    else if (z == 1) gemm_body<2>(Ak, Wk, bk, ok, psm, bm, bn);
    else             gemm_body<1>(Av, Wv, bv, ov, psm, bm, bn);
}

__global__ __launch_bounds__(256, 2)
void out_gemm(const float* __restrict__ A, const float* __restrict__ W,
              const float* __restrict__ bias, float* __restrict__ out)
{
    extern __shared__ float psm[];
    gemm_body<0>(A, W, bias, out, psm, blockIdx.y * 128, blockIdx.x * 128);
}

// ---------------------------------------------------------------------------
// Flash attention: block = 128 q x (tiles of 64 j), 256 threads, 8q x 4j.
// Kt double-buffered; commits scheduled a full tile ahead (cp_wait<1>).
// Smem (floats): Qs[64][128] | Kt 2x[64][64] | Vs[64][64] | Ps[64][128]
//              = 112 KB -> 2 CTAs/SM.
// ---------------------------------------------------------------------------
#define NT (Tq/64)                 // 32 tiles
#define ATT_SMEM ((8192 + 2*4096 + 4096 + 8192)*4)   // 114688 B

__global__ __launch_bounds__(256, 2)
void attn_kernel(const float* __restrict__ Qd, const float* __restrict__ Kd,
                 const float* __restrict__ V, float* __restrict__ O)
{
    extern __shared__ float sm[];
    float* Qs  = sm;             // [64][128]
    float* Kt0 = sm + 8192;      // [64][64] stage 0
    float* Kt1 = sm + 12288;     // [64][64] stage 1
    float* Vs  = sm + 16384;     // [64][64]
    float* Ps  = sm + 20480;     // [64][128] xor-swizzled cols
    const uint32_t ktb[2] = { smem_u32(Kt0), smem_u32(Kt1) };
    const uint32_t vsb = smem_u32(Vs);

    const int tid = threadIdx.x;
    const int tx  = tid & 15;          // j: tx*4..+3
    const int ty  = tid >> 4;          // q: {ty*4, 64+ty*4}
    const int qt  = blockIdx.x * 128;
    const int h   = blockIdx.y;
    const int b   = blockIdx.z;

    const size_t dmaj = ((size_t)(b*Hq + h) * HDq) * Tq;
    const float* Qb = Qd + dmaj;
    const float* Kb = Kd + dmaj;
    const float* Vb = V + ((size_t)(b*Hq + h) * Tq) * HDq;

    auto cpK = [&](int t) {            // Kt[64d][64j] into stage t&1
        int kt0 = t * 64;
        uint32_t base = ktb[t & 1];
        #pragma unroll
        for (int u = 0; u < 4; u++) {
            int idx = tid + u*256;
            int r = idx >> 4, c = idx & 15;
            cpa16(base + (uint32_t)(r*64 + c*4)*4, Kb + (size_t)r * Tq + kt0 + c*4);
        }
    };
    auto cpV = [&](int t) {            // Vs[64j][64d]
        int kt0 = t * 64;
        #pragma unroll
        for (int u = 0; u < 4; u++) {
            int idx = tid + u*256;
            int jr = idx >> 4, d4 = idx & 15;
            cpa16(vsb + (uint32_t)(jr*64 + d4*4)*4,
                  Vb + (size_t)(kt0 + jr) * HDq + d4*4);
        }
    };

    // Prologue: K(0), V(0), K(1) in flight
    cpK(0); cp_commit();
    cpV(0); cp_commit();
    cpK(1); cp_commit();

    // Q tile [64d][128q], scaled by 1/8 * log2(e)
    {
        const float qscale = 0.125f * 1.4426950408889634f;
        #pragma unroll
        for (int u = 0; u < 8; u++) {
            int idx = tid + u*256;
            int d = idx >> 5, c4 = idx & 31;
            float4 v = *reinterpret_cast<const float4*>(Qb + (size_t)d * Tq + qt + c4*4);
            v.x *= qscale; v.y *= qscale; v.z *= qscale; v.w *= qscale;
            *reinterpret_cast<float4*>(&Qs[d*128 + c4*4]) = v;
        }
    }

    float o[8][4] = {};
    float m[8], l[8];
    #pragma unroll
    for (int i = 0; i < 8; i++) { m[i] = -INFINITY; l[i] = 0.f; }

    const int ssw  = tx & 7;
    const int scol = (ty ^ ssw) << 2;

    for (int t = 0; t < NT; t++) {
        // K(t), V(t) committed >= 1 tile ago; K(t+1) may stay in flight
        if (t >= NT-2) cp_wait<0>(); else cp_wait<1>();
        __syncthreads();

        const float* Kt = (t & 1) ? Kt1 : Kt0;

        // S = Q^T K : s[8 q][4 j]
        float s[8][4] = {};
        #pragma unroll 8
        for (int c = 0; c < 64; c++) {
            float4 a0 = *reinterpret_cast<const float4*>(&Qs[c*128 + ty*4]);
            float4 a1 = *reinterpret_cast<const float4*>(&Qs[c*128 + 64 + ty*4]);
            float4 b4 = *reinterpret_cast<const float4*>(&Kt[c*64 + tx*4]);
            const float a[8] = {a0.x,a0.y,a0.z,a0.w, a1.x,a1.y,a1.z,a1.w};
            const float bb[4] = {b4.x, b4.y, b4.z, b4.w};
            #pragma unroll
            for (int i = 0; i < 8; i++)
                #pragma unroll
                for (int j = 0; j < 4; j++)
                    s[i][j] += a[i] * bb[j];
        }

        // Online softmax (exp2 domain)
        #pragma unroll
        for (int i = 0; i < 8; i++) {
            float rm = fmaxf(fmaxf(s[i][0], s[i][1]), fmaxf(s[i][2], s[i][3]));
            #pragma unroll
            for (int x = 1; x < 16; x <<= 1)
                rm = fmaxf(rm, __shfl_xor_sync(0xffffffffu, rm, x));
            float mnew = fmaxf(m[i], rm);
            float alpha = ex2(m[i] - mnew);
            m[i] = mnew;
            float rs = 0.f;
            #pragma unroll
            for (int j = 0; j < 4; j++) {
                s[i][j] = ex2(s[i][j] - mnew);
                rs += s[i][j];
            }
            #pragma unroll
            for (int x = 1; x < 16; x <<= 1)
                rs += __shfl_xor_sync(0xffffffffu, rs, x);
            l[i] = l[i] * alpha + rs;
            #pragma unroll
            for (int c = 0; c < 4; c++) o[i][c] *= alpha;
        }

        // Store P[j][q] swizzled
        #pragma unroll
        for (int jj = 0; jj < 4; jj++) {
            int j = tx*4 + jj;
            *reinterpret_cast<float4*>(&Ps[j*128 + scol]) =
                make_float4(s[0][jj], s[1][jj], s[2][jj], s[3][jj]);
            *reinterpret_cast<float4*>(&Ps[j*128 + 64 + scol]) =
                make_float4(s[4][jj], s[5][jj], s[6][jj], s[7][jj]);
        }
        __syncthreads();               // P visible

        // O += P V : o[8 q][4 d]
        #pragma unroll 2
        for (int jg = 0; jg < 16; jg++) {
            const int rcol = ((ty ^ (jg & 7)) << 2);
            const float* Pb  = &Ps[jg*4*128];
            const float* Vbv = &Vs[jg*4*64 + tx*4];
            #pragma unroll
            for (int jj = 0; jj < 4; jj++) {
                float4 a0 = *reinterpret_cast<const float4*>(&Pb[jj*128 + rcol]);
                float4 a1 = *reinterpret_cast<const float4*>(&Pb[jj*128 + 64 + rcol]);
                float4 v4 = *reinterpret_cast<const float4*>(&Vbv[jj*64]);
                const float a[8] = {a0.x,a0.y,a0.z,a0.w, a1.x,a1.y,a1.z,a1.w};
                const float bb[4] = {v4.x, v4.y, v4.z, v4.w};
                #pragma unroll
                for (int i = 0; i < 8; i++)
                    #pragma unroll
                    for (int c = 0; c < 4; c++)
                        o[i][c] += a[i] * bb[c];
            }
        }
        __syncthreads();               // Vs reads done

        if (t + 1 < NT) { cpV(t + 1); cp_commit(); }
        if (t + 2 < NT) { cpK(t + 2); cp_commit(); }
    }

    // Write O (merged heads)
    #pragma unroll
    for (int i = 0; i < 8; i++) {
        float inv = 1.f / l[i];
        int q = qt + ((i < 4) ? (ty*4 + i) : (64 + ty*4 + i - 4));
        float4 v;
        v.x = o[i][0]*inv; v.y = o[i][1]*inv; v.z = o[i][2]*inv; v.w = o[i][3]*inv;
        *reinterpret_cast<float4*>(
            &O[((size_t)b*Tq + q) * Cq + h*HDq + tx*4]) = v;
    }
}

// ---------------------------------------------------------------------------
// Launch
// ---------------------------------------------------------------------------
extern "C" void kernel_launch(void* const* d_in, const int* in_sizes, int n_in,
                              void* d_out, int out_size)
{
    (void)in_sizes; (void)n_in; (void)out_size;
    const float* queries = (const float*)d_in[0];
    const float* keys    = (const float*)d_in[1];
    const float* values  = (const float*)d_in[2];
    const float* Wq = (const float*)d_in[3];
    const float* bq = (const float*)d_in[4];
    const float* Wk = (const float*)d_in[5];
    const float* bk = (const float*)d_in[6];
    const float* Wv = (const float*)d_in[7];
    const float* bv = (const float*)d_in[8];
    const float* Wo = (const float*)d_in[9];
    const float* bo = (const float*)d_in[10];
    float* out = (float*)d_out;

    float *pQ, *pK, *pV, *pO;
    cudaGetSymbolAddress((void**)&pQ, g_Qd);
    cudaGetSymbolAddress((void**)&pK, g_Kd);
    cudaGetSymbolAddress((void**)&pV, g_V);
    cudaGetSymbolAddress((void**)&pO, g_O);

    cudaFuncSetAttribute(attn_kernel, cudaFuncAttributeMaxDynamicSharedMemorySize, ATT_SMEM);
    cudaFuncSetAttribute(qkv_gemm,  cudaFuncAttributeMaxDynamicSharedMemorySize, PG_SMEM);
    cudaFuncSetAttribute(out_gemm,  cudaFuncAttributeMaxDynamicSharedMemorySize, PG_SMEM);

    dim3 gqkv(Cq/128, Mq/128, 3);      // (8, 32, 3) = 768 CTAs
    qkv_gemm<<<gqkv, 256, PG_SMEM>>>(queries, keys, values,
                                     Wq, bq, Wk, bk, Wv, bv,
                                     pQ, pK, pV);

    dim3 ga(Tq/128, Hq, Bq);           // (16, 16, 2)
    attn_kernel<<<ga, 256, ATT_SMEM>>>(pQ, pK, pV, pO);

    dim3 gg(Cq/128, Mq/128);           // (8, 32)
    out_gemm<<<gg, 256, PG_SMEM>>>(pO, Wo, bo, out);
}